// round 3
// baseline (speedup 1.0000x reference)
#include <cuda_runtime.h>
#include <math.h>

#define H2d 4
#define Bsz 16
#define Cc 64
#define Nn 64
#define Dd 512
#define Ll (Nn*Cc)            // 4096
#define M3 (3*Dd)             // 1536
#define LDm 68                // padded smem leading dim (floats)
#define SCALE_ATT 0.125f      // 1/sqrt(64)
#define SPD_EPSF 1e-5f

// ---------------- scratch (static device memory; no allocations) ----------------
__device__ float g_qkv[(size_t)Bsz * Ll * M3];   // (B, L, 3*512) = 402 MB
__device__ float g_attn[(size_t)Bsz * Ll * Dd];  // (B, L, 512)   = 134 MB

// =================================================================
// SGEMM: C[M,N] = A[M,K] @ W[N,K]^T + bias[N]
// 128x128 block tile, BK=8, 8x8 per thread, 256 threads
// =================================================================
__global__ __launch_bounds__(256, 2) void sgemm_bias(
    const float* __restrict__ A, const float* __restrict__ W,
    const float* __restrict__ bias, float* __restrict__ C,
    int M, int N, int K)
{
    __shared__ float As[8][128];
    __shared__ float Bs[8][128];
    const int tid = threadIdx.x;
    const int tx = tid & 15, ty = tid >> 4;
    const int bc = blockIdx.x, br = blockIdx.y;
    const float* Ab = A + (size_t)br * 128 * K;
    const float* Wb = W + (size_t)bc * 128 * K;
    const int lr = tid >> 1, lc4 = (tid & 1) * 4;

    float acc[8][8];
#pragma unroll
    for (int i = 0; i < 8; i++)
#pragma unroll
        for (int j = 0; j < 8; j++) acc[i][j] = 0.f;

    for (int kt = 0; kt < K; kt += 8) {
        float4 av = *(const float4*)(Ab + (size_t)lr * K + kt + lc4);
        float4 bv = *(const float4*)(Wb + (size_t)lr * K + kt + lc4);
        As[lc4 + 0][lr] = av.x; As[lc4 + 1][lr] = av.y;
        As[lc4 + 2][lr] = av.z; As[lc4 + 3][lr] = av.w;
        Bs[lc4 + 0][lr] = bv.x; Bs[lc4 + 1][lr] = bv.y;
        Bs[lc4 + 2][lr] = bv.z; Bs[lc4 + 3][lr] = bv.w;
        __syncthreads();
#pragma unroll
        for (int k = 0; k < 8; k++) {
            float4 a0 = *(const float4*)&As[k][ty * 8];
            float4 a1 = *(const float4*)&As[k][ty * 8 + 4];
            float4 b0 = *(const float4*)&Bs[k][tx * 8];
            float4 b1 = *(const float4*)&Bs[k][tx * 8 + 4];
            float am[8] = {a0.x, a0.y, a0.z, a0.w, a1.x, a1.y, a1.z, a1.w};
            float bn[8] = {b0.x, b0.y, b0.z, b0.w, b1.x, b1.y, b1.z, b1.w};
#pragma unroll
            for (int i = 0; i < 8; i++)
#pragma unroll
                for (int j = 0; j < 8; j++) acc[i][j] += am[i] * bn[j];
        }
        __syncthreads();
    }

    const int ccol = bc * 128 + tx * 8;
    float b8[8];
#pragma unroll
    for (int j = 0; j < 8; j++) b8[j] = bias[ccol + j];
#pragma unroll
    for (int i = 0; i < 8; i++) {
        size_t row = (size_t)br * 128 + ty * 8 + i;
        float4 v0 = make_float4(acc[i][0] + b8[0], acc[i][1] + b8[1],
                                acc[i][2] + b8[2], acc[i][3] + b8[3]);
        float4 v1 = make_float4(acc[i][4] + b8[4], acc[i][5] + b8[5],
                                acc[i][6] + b8[6], acc[i][7] + b8[7]);
        *(float4*)(C + row * N + ccol) = v0;
        *(float4*)(C + row * N + ccol + 4) = v1;
    }
}

// =================================================================
// helpers: 64x64 smem matmul (row-major, LD=LDm), 16x16 threads, 4x4/thread
// dst = dscale * (Am @ Bm) + diagadd * I   (dst must not alias Am/Bm)
// =================================================================
__device__ __forceinline__ void mm64(float* __restrict__ dst,
                                     const float* __restrict__ Am,
                                     const float* __restrict__ Bm,
                                     int tx, int ty, float dscale, float diagadd)
{
    float acc[4][4] = {};
#pragma unroll 8
    for (int k = 0; k < 64; k++) {
        float4 bv = *(const float4*)(Bm + k * LDm + 4 * tx);
        float a0 = Am[(4 * ty + 0) * LDm + k];
        float a1 = Am[(4 * ty + 1) * LDm + k];
        float a2 = Am[(4 * ty + 2) * LDm + k];
        float a3 = Am[(4 * ty + 3) * LDm + k];
        acc[0][0] += a0 * bv.x; acc[0][1] += a0 * bv.y; acc[0][2] += a0 * bv.z; acc[0][3] += a0 * bv.w;
        acc[1][0] += a1 * bv.x; acc[1][1] += a1 * bv.y; acc[1][2] += a1 * bv.z; acc[1][3] += a1 * bv.w;
        acc[2][0] += a2 * bv.x; acc[2][1] += a2 * bv.y; acc[2][2] += a2 * bv.z; acc[2][3] += a2 * bv.w;
        acc[3][0] += a3 * bv.x; acc[3][1] += a3 * bv.y; acc[3][2] += a3 * bv.z; acc[3][3] += a3 * bv.w;
    }
#pragma unroll
    for (int i = 0; i < 4; i++)
#pragma unroll
        for (int j = 0; j < 4; j++) {
            int r = 4 * ty + i, c = 4 * tx + j;
            dst[r * LDm + c] = acc[i][j] * dscale + ((r == c) ? diagadd : 0.f);
        }
    __syncthreads();
}

// row softmax over 64 cols held as 4x4 register tile; the 16 threads of a row
// are a contiguous 16-lane segment -> width-16 xor shuffles
__device__ __forceinline__ void softmax_rows(float acc[4][4])
{
#pragma unroll
    for (int i = 0; i < 4; i++) {
        float m = fmaxf(fmaxf(acc[i][0], acc[i][1]), fmaxf(acc[i][2], acc[i][3]));
#pragma unroll
        for (int off = 8; off > 0; off >>= 1)
            m = fmaxf(m, __shfl_xor_sync(0xffffffffu, m, off, 16));
        float s = 0.f;
#pragma unroll
        for (int j = 0; j < 4; j++) { acc[i][j] = __expf(acc[i][j] - m); s += acc[i][j]; }
#pragma unroll
        for (int off = 8; off > 0; off >>= 1)
            s += __shfl_xor_sync(0xffffffffu, s, off, 16);
        float inv = 1.f / s;
#pragma unroll
        for (int j = 0; j < 4; j++) acc[i][j] *= inv;
    }
}

// =================================================================
// Temporal attention: CTA per (b, c, h<4); attention over N=64 tokens
// rows l = n*C + c ; writes g_attn[b, l, h*64 + e]
// =================================================================
__global__ __launch_bounds__(256, 2) void temporal_attn()
{
    extern __shared__ float smT[];
    float* Q  = smT;
    float* Kt = Q  + 64 * LDm;
    float* V  = Kt + 64 * LDm;
    float* P  = V  + 64 * LDm;
    const int tid = threadIdx.x, tx = tid & 15, ty = tid >> 4;
    const int h = blockIdx.x & 3;
    const int c = (blockIdx.x >> 2) & 63;
    const int b = blockIdx.x >> 8;

    const float* qk = g_qkv + (size_t)b * Ll * M3 + h * 64;
#pragma unroll
    for (int it = 0; it < 16; it++) {
        int idx = it * 256 + tid;
        int nn = idx >> 6, e = idx & 63;
        const float* p = qk + (size_t)(nn * Cc + c) * M3 + e;
        Q [nn * LDm + e]  = p[0];
        Kt[e  * LDm + nn] = p[Dd];
        V [nn * LDm + e]  = p[2 * Dd];
    }
    __syncthreads();

    // scores = Q @ K^T * scale
    float acc[4][4] = {};
#pragma unroll 8
    for (int k = 0; k < 64; k++) {
        float4 bv = *(const float4*)(Kt + k * LDm + 4 * tx);
        float a0 = Q[(4 * ty + 0) * LDm + k];
        float a1 = Q[(4 * ty + 1) * LDm + k];
        float a2 = Q[(4 * ty + 2) * LDm + k];
        float a3 = Q[(4 * ty + 3) * LDm + k];
        acc[0][0] += a0 * bv.x; acc[0][1] += a0 * bv.y; acc[0][2] += a0 * bv.z; acc[0][3] += a0 * bv.w;
        acc[1][0] += a1 * bv.x; acc[1][1] += a1 * bv.y; acc[1][2] += a1 * bv.z; acc[1][3] += a1 * bv.w;
        acc[2][0] += a2 * bv.x; acc[2][1] += a2 * bv.y; acc[2][2] += a2 * bv.z; acc[2][3] += a2 * bv.w;
        acc[3][0] += a3 * bv.x; acc[3][1] += a3 * bv.y; acc[3][2] += a3 * bv.z; acc[3][3] += a3 * bv.w;
    }
#pragma unroll
    for (int i = 0; i < 4; i++)
#pragma unroll
        for (int j = 0; j < 4; j++) acc[i][j] *= SCALE_ATT;

    softmax_rows(acc);

#pragma unroll
    for (int i = 0; i < 4; i++)
#pragma unroll
        for (int j = 0; j < 4; j++)
            P[(4 * ty + i) * LDm + 4 * tx + j] = acc[i][j];
    __syncthreads();

    // out = P @ V
    float o[4][4] = {};
#pragma unroll 8
    for (int k = 0; k < 64; k++) {
        float4 bv = *(const float4*)(V + k * LDm + 4 * tx);
        float a0 = P[(4 * ty + 0) * LDm + k];
        float a1 = P[(4 * ty + 1) * LDm + k];
        float a2 = P[(4 * ty + 2) * LDm + k];
        float a3 = P[(4 * ty + 3) * LDm + k];
        o[0][0] += a0 * bv.x; o[0][1] += a0 * bv.y; o[0][2] += a0 * bv.z; o[0][3] += a0 * bv.w;
        o[1][0] += a1 * bv.x; o[1][1] += a1 * bv.y; o[1][2] += a1 * bv.z; o[1][3] += a1 * bv.w;
        o[2][0] += a2 * bv.x; o[2][1] += a2 * bv.y; o[2][2] += a2 * bv.z; o[2][3] += a2 * bv.w;
        o[3][0] += a3 * bv.x; o[3][1] += a3 * bv.y; o[3][2] += a3 * bv.z; o[3][3] += a3 * bv.w;
    }
#pragma unroll
    for (int i = 0; i < 4; i++) {
        size_t l = (size_t)(4 * ty + i) * Cc + c;
        *(float4*)(g_attn + ((size_t)b * Ll + l) * Dd + h * 64 + 4 * tx) =
            make_float4(o[i][0], o[i][1], o[i][2], o[i][3]);
    }
}

// =================================================================
// Spatial branch: CTA per (b, n).
// Phase A: S = xs xs^T/D + eps I; A = S + I;
//          Y = A^{-1} via Newton-Schulz (Gershgorin-scaled init, 6 iters);
//          Z = I - 2Y  (spec in (-1,1));  Lm = logm(S) = 2*atanh(Z) via
//          10-term Gregory series (Horner in W = Z^2).
// Phase B: 4 spatial heads of attention with bias = head_scale[h]*Lm.
// =================================================================
__global__ __launch_bounds__(256, 2) void spatial_riemann(
    const float* __restrict__ x, const float* __restrict__ head_scales)
{
    extern __shared__ float smS[];
    float* B0 = smS;              // A -> W -> Q
    float* B1 = B0 + 64 * LDm;    // Y -> P(series) -> P(softmax)
    float* B2 = B1 + 64 * LDm;    // chunk/T1 -> Z -> Kt
    float* B3 = B2 + 64 * LDm;    // chunkT/T2 -> series tmp -> V
    float* LM = B3 + 64 * LDm;    // log-matrix
    float* red = LM + 64 * LDm;   // 256 floats
    __shared__ float s_alpha;

    const int tid = threadIdx.x, tx = tid & 15, ty = tid >> 4;
    const int n = blockIdx.x & 63, b = blockIdx.x >> 6;
    const float* xb = x + ((size_t)b * Ll + n * Cc) * Dd;

    // ---- build A = S + I ----
    float sacc[4][4] = {};
    for (int kc = 0; kc < 8; kc++) {
#pragma unroll
        for (int it = 0; it < 16; it++) {
            int idx = it * 256 + tid;
            int r = idx >> 6, col = idx & 63;
            float v = xb[(size_t)r * Dd + kc * 64 + col];
            B2[r * LDm + col] = v;     // Xc
            B3[col * LDm + r] = v;     // Xc^T
        }
        __syncthreads();
#pragma unroll 8
        for (int k = 0; k < 64; k++) {
            float4 bv = *(const float4*)(B3 + k * LDm + 4 * tx);
            float a0 = B2[(4 * ty + 0) * LDm + k];
            float a1 = B2[(4 * ty + 1) * LDm + k];
            float a2 = B2[(4 * ty + 2) * LDm + k];
            float a3 = B2[(4 * ty + 3) * LDm + k];
            sacc[0][0] += a0 * bv.x; sacc[0][1] += a0 * bv.y; sacc[0][2] += a0 * bv.z; sacc[0][3] += a0 * bv.w;
            sacc[1][0] += a1 * bv.x; sacc[1][1] += a1 * bv.y; sacc[1][2] += a1 * bv.z; sacc[1][3] += a1 * bv.w;
            sacc[2][0] += a2 * bv.x; sacc[2][1] += a2 * bv.y; sacc[2][2] += a2 * bv.z; sacc[2][3] += a2 * bv.w;
            sacc[3][0] += a3 * bv.x; sacc[3][1] += a3 * bv.y; sacc[3][2] += a3 * bv.z; sacc[3][3] += a3 * bv.w;
        }
        __syncthreads();
    }
#pragma unroll
    for (int i = 0; i < 4; i++)
#pragma unroll
        for (int j = 0; j < 4; j++) {
            int r = 4 * ty + i, c = 4 * tx + j;
            float v = sacc[i][j] * (1.f / (float)Dd);
            if (r == c) v += 1.f + SPD_EPSF;   // S + eps I, then +I for A
            B0[r * LDm + c] = v;
        }
    __syncthreads();

    // ---- Gershgorin bound -> alpha ----
    {
        int r = tid >> 2, seg = tid & 3;
        float s = 0.f;
#pragma unroll
        for (int j = 0; j < 16; j++) s += fabsf(B0[r * LDm + seg * 16 + j]);
        red[tid] = s;
    }
    __syncthreads();
    if (tid == 0) {
        float rmax = 0.f;
        for (int r = 0; r < 64; r++)
            rmax = fmaxf(rmax, red[4 * r] + red[4 * r + 1] + red[4 * r + 2] + red[4 * r + 3]);
        s_alpha = 2.f / (1.f + rmax);
    }
    __syncthreads();
    float alpha = s_alpha;

    // Y = alpha I
#pragma unroll
    for (int i = 0; i < 4; i++)
#pragma unroll
        for (int j = 0; j < 4; j++) {
            int r = 4 * ty + i, c = 4 * tx + j;
            B1[r * LDm + c] = (r == c) ? alpha : 0.f;
        }
    __syncthreads();

    // ---- Newton-Schulz: Y <- 2Y - Y A Y, 6 iterations ----
    for (int it = 0; it < 6; it++) {
        mm64(B2, B0, B1, tx, ty, 1.f, 0.f);   // T1 = A*Y
        mm64(B3, B1, B2, tx, ty, 1.f, 0.f);   // T2 = Y*T1
#pragma unroll
        for (int i = 0; i < 4; i++)
#pragma unroll
            for (int j = 0; j < 4; j++) {
                int r = 4 * ty + i, c = 4 * tx + j;
                B1[r * LDm + c] = 2.f * B1[r * LDm + c] - B3[r * LDm + c];
            }
        __syncthreads();
    }

    // Z = I - 2Y -> B2
#pragma unroll
    for (int i = 0; i < 4; i++)
#pragma unroll
        for (int j = 0; j < 4; j++) {
            int r = 4 * ty + i, c = 4 * tx + j;
            B2[r * LDm + c] = ((r == c) ? 1.f : 0.f) - 2.f * B1[r * LDm + c];
        }
    __syncthreads();

    // W = Z*Z -> B0
    mm64(B0, B2, B2, tx, ty, 1.f, 0.f);

    // Gregory/Horner: P = sum_{m=0}^{9} W^m/(2m+1), start P = I/19 in B3
#pragma unroll
    for (int i = 0; i < 4; i++)
#pragma unroll
        for (int j = 0; j < 4; j++) {
            int r = 4 * ty + i, c = 4 * tx + j;
            B3[r * LDm + c] = (r == c) ? (1.f / 19.f) : 0.f;
        }
    __syncthreads();
    {
        float* cur = B3; float* oth = B1;
        for (int m = 8; m >= 0; m--) {
            mm64(oth, cur, B0, tx, ty, 1.f, 1.f / (float)(2 * m + 1));
            float* t = cur; cur = oth; oth = t;
        }
        // after 9 swaps, P is in B1 (== cur)
        mm64(LM, B2, cur, tx, ty, 2.f, 0.f);   // Lm = 2 * Z * P
    }

    // ---- Phase B: spatial attention with bias = hs * Lm ----
    const float* qk = g_qkv + (size_t)b * Ll * M3 + H2d * 64;
    for (int h = 0; h < H2d; h++) {
        float hs = head_scales[h];
#pragma unroll
        for (int it = 0; it < 16; it++) {
            int idx = it * 256 + tid;
            int r = idx >> 6, e = idx & 63;
            const float* p = qk + (size_t)(n * Cc + r) * M3 + h * 64 + e;
            B0[r * LDm + e] = p[0];        // Q
            B2[e * LDm + r] = p[Dd];       // K^T
            B3[r * LDm + e] = p[2 * Dd];   // V
        }
        __syncthreads();

        float a4[4][4] = {};
#pragma unroll 8
        for (int k = 0; k < 64; k++) {
            float4 bv = *(const float4*)(B2 + k * LDm + 4 * tx);
            float a0 = B0[(4 * ty + 0) * LDm + k];
            float a1 = B0[(4 * ty + 1) * LDm + k];
            float a2 = B0[(4 * ty + 2) * LDm + k];
            float a3 = B0[(4 * ty + 3) * LDm + k];
            a4[0][0] += a0 * bv.x; a4[0][1] += a0 * bv.y; a4[0][2] += a0 * bv.z; a4[0][3] += a0 * bv.w;
            a4[1][0] += a1 * bv.x; a4[1][1] += a1 * bv.y; a4[1][2] += a1 * bv.z; a4[1][3] += a1 * bv.w;
            a4[2][0] += a2 * bv.x; a4[2][1] += a2 * bv.y; a4[2][2] += a2 * bv.z; a4[2][3] += a2 * bv.w;
            a4[3][0] += a3 * bv.x; a4[3][1] += a3 * bv.y; a4[3][2] += a3 * bv.z; a4[3][3] += a3 * bv.w;
        }
#pragma unroll
        for (int i = 0; i < 4; i++)
#pragma unroll
            for (int j = 0; j < 4; j++)
                a4[i][j] = a4[i][j] * SCALE_ATT + hs * LM[(4 * ty + i) * LDm + 4 * tx + j];

        softmax_rows(a4);

#pragma unroll
        for (int i = 0; i < 4; i++)
#pragma unroll
            for (int j = 0; j < 4; j++)
                B1[(4 * ty + i) * LDm + 4 * tx + j] = a4[i][j];
        __syncthreads();

        float o[4][4] = {};
#pragma unroll 8
        for (int k = 0; k < 64; k++) {
            float4 bv = *(const float4*)(B3 + k * LDm + 4 * tx);
            float a0 = B1[(4 * ty + 0) * LDm + k];
            float a1 = B1[(4 * ty + 1) * LDm + k];
            float a2 = B1[(4 * ty + 2) * LDm + k];
            float a3 = B1[(4 * ty + 3) * LDm + k];
            o[0][0] += a0 * bv.x; o[0][1] += a0 * bv.y; o[0][2] += a0 * bv.z; o[0][3] += a0 * bv.w;
            o[1][0] += a1 * bv.x; o[1][1] += a1 * bv.y; o[1][2] += a1 * bv.z; o[1][3] += a1 * bv.w;
            o[2][0] += a2 * bv.x; o[2][1] += a2 * bv.y; o[2][2] += a2 * bv.z; o[2][3] += a2 * bv.w;
            o[3][0] += a3 * bv.x; o[3][1] += a3 * bv.y; o[3][2] += a3 * bv.z; o[3][3] += a3 * bv.w;
        }
#pragma unroll
        for (int i = 0; i < 4; i++) {
            size_t l = (size_t)n * Cc + 4 * ty + i;
            *(float4*)(g_attn + ((size_t)b * Ll + l) * Dd + (H2d + h) * 64 + 4 * tx) =
                make_float4(o[i][0], o[i][1], o[i][2], o[i][3]);
        }
        __syncthreads();
    }
}

// =================================================================
// launch
// =================================================================
extern "C" void kernel_launch(void* const* d_in, const int* in_sizes, int n_in,
                              void* d_out, int out_size)
{
    const float* x     = (const float*)d_in[0];
    const float* qkv_w = (const float*)d_in[1];
    const float* qkv_b = (const float*)d_in[2];
    const float* fc_w  = (const float*)d_in[3];
    const float* fc_b  = (const float*)d_in[4];
    const float* hsc   = (const float*)d_in[5];
    float* out = (float*)d_out;

    float* p_qkv = nullptr;
    float* p_attn = nullptr;
    cudaGetSymbolAddress((void**)&p_qkv, g_qkv);
    cudaGetSymbolAddress((void**)&p_attn, g_attn);

    const int smemT = 4 * 64 * LDm * (int)sizeof(float);            // 69632
    const int smemS = 5 * 64 * LDm * (int)sizeof(float) + 256 * 4;  // 88064
    cudaFuncSetAttribute(temporal_attn, cudaFuncAttributeMaxDynamicSharedMemorySize, smemT);
    cudaFuncSetAttribute(spatial_riemann, cudaFuncAttributeMaxDynamicSharedMemorySize, smemS);

    // 1) QKV projection: (65536 x 1536) = x @ qkv_w^T + qkv_b
    {
        dim3 grid(M3 / 128, (Bsz * Ll) / 128);
        sgemm_bias<<<grid, 256>>>(x, qkv_w, qkv_b, p_qkv, Bsz * Ll, M3, Dd);
    }
    // 2) temporal heads (0..3)
    temporal_attn<<<Bsz * Cc * H2d, 256, smemT>>>();
    // 3) SPD log bias + spatial heads (4..7), fused
    spatial_riemann<<<Bsz * Nn, 256, smemS>>>(x, hsc);
    // 4) output projection: (65536 x 512) = attn @ fc_w^T + fc_b
    {
        dim3 grid(Dd / 128, (Bsz * Ll) / 128);
        sgemm_bias<<<grid, 256>>>(p_attn, fc_w, fc_b, out, Bsz * Ll, Dd, Dd);
    }
}

// round 6
// speedup vs baseline: 1.6610x; 1.6610x over previous
#include <cuda_runtime.h>
#include <cuda_bf16.h>
#include <cstdint>
#include <cstddef>
#include <math.h>

#define H2d 4
#define Bsz 16
#define Cc 64
#define Nn 64
#define Dd 512
#define Ll (Nn*Cc)            // 4096
#define M3 (3*Dd)             // 1536
#define LDm 68                // padded smem leading dim (floats)
#define SCALE_ATT 0.125f      // 1/sqrt(64)
#define SPD_EPSF 1e-5f

#define MROWS (Bsz*Ll)        // 65536
#define K3 1536               // split-K: 3 * 512
#define BK 32                 // bf16 K per chunk
#define BMg 128
#define BNg 128
#define APITCH 40             // bf16 units per smem row (32 + 8 pad) -> 80B pitch
#define STG_TILE (128*APITCH) // bf16 elems per tile per stage
#define STAGES 3

// ---------------- scratch (static device memory; no allocations) ----------------
__device__ float g_qkv[(size_t)Bsz * Ll * M3];            // (B, L, 1536) fp32
__device__ float g_attn[(size_t)Bsz * Ll * Dd];           // (B, L, 512)  fp32
__device__ __nv_bfloat16 g_abuf[(size_t)MROWS * K3];      // bf16x3 activations
__device__ __nv_bfloat16 g_wbuf[(size_t)M3 * K3];         // bf16x3 weights

// =================================================================
// PTX helpers (plain PTX only: cp.async + mma.sync, valid on sm_103)
// =================================================================
__device__ __forceinline__ uint32_t smem_u32(const void* p) {
    uint32_t a;
    asm("{ .reg .u64 t; cvta.to.shared.u64 t, %1; cvt.u32.u64 %0, t; }" : "=r"(a) : "l"(p));
    return a;
}
#define CP_ASYNC16(dst, src) \
    asm volatile("cp.async.cg.shared.global [%0], [%1], 16;" :: "r"(dst), "l"(src))
#define CP_COMMIT() asm volatile("cp.async.commit_group;" ::: "memory")
#define CP_WAIT1()  asm volatile("cp.async.wait_group 1;" ::: "memory")
#define CP_WAIT0()  asm volatile("cp.async.wait_group 0;" ::: "memory")

__device__ __forceinline__ void mma16816(float c[4], uint32_t a0, uint32_t a1,
                                         uint32_t a2, uint32_t a3,
                                         uint32_t b0, uint32_t b1) {
    asm volatile(
        "mma.sync.aligned.m16n8k16.row.col.f32.bf16.bf16.f32 "
        "{%0,%1,%2,%3}, {%4,%5,%6,%7}, {%8,%9}, {%0,%1,%2,%3};"
        : "+f"(c[0]), "+f"(c[1]), "+f"(c[2]), "+f"(c[3])
        : "r"(a0), "r"(a1), "r"(a2), "r"(a3), "r"(b0), "r"(b1));
}

// =================================================================
// fp32 -> bf16x3 split conversion.
// mode 0 (activations): segs = [hi | lo | hi]
// mode 1 (weights):     segs = [hi | hi | lo]
// K-concatenated product gives hi*hi + lo*hi + hi*lo.
// =================================================================
__global__ void conv_split(const float* __restrict__ src, __nv_bfloat16* __restrict__ dst,
                           size_t total, int mode)
{
    size_t i = (size_t)blockIdx.x * blockDim.x + threadIdx.x;
    size_t e = i * 2;
    if (e >= total) return;
    size_t m = e >> 9;          // /512
    int k = (int)(e & 511);
    float2 v = *(const float2*)(src + e);
    __nv_bfloat16 h0 = __float2bfloat16(v.x);
    __nv_bfloat16 h1 = __float2bfloat16(v.y);
    __nv_bfloat16 l0 = __float2bfloat16(v.x - __bfloat162float(h0));
    __nv_bfloat16 l1 = __float2bfloat16(v.y - __bfloat162float(h1));
    __nv_bfloat162 hh; hh.x = h0; hh.y = h1;
    __nv_bfloat162 ll; ll.x = l0; ll.y = l1;
    __nv_bfloat16* base = dst + m * K3 + k;
    *(__nv_bfloat162*)(base)        = hh;
    *(__nv_bfloat162*)(base + 512)  = (mode == 0) ? ll : hh;
    *(__nv_bfloat162*)(base + 1024) = (mode == 0) ? hh : ll;
}

// =================================================================
// mma.sync bf16 GEMM: C[M, Nout] = A[M, K3] @ W[Nout, K3]^T + bias
// 128x128 CTA tile, 8 warps of 64x32, BK=32, 3-stage cp.async.
// =================================================================
__global__ __launch_bounds__(256) void gemm_mma(
    const __nv_bfloat16* __restrict__ A, const __nv_bfloat16* __restrict__ W,
    const float* __restrict__ bias, float* __restrict__ C, int Nout)
{
    extern __shared__ __nv_bfloat16 smg[];
    const int tid = threadIdx.x;
    const int wid = tid >> 5, lane = tid & 31;
    const int g = lane >> 2, tig = lane & 3;
    const int warp_m = wid >> 2, warp_n = wid & 3;     // 2 x 4 warps
    const int bc = blockIdx.x, br = blockIdx.y;

    const __nv_bfloat16* gAb = A + (size_t)(br * BMg) * K3;
    const __nv_bfloat16* gBb = W + (size_t)(bc * BNg) * K3;

    const uint32_t smb = smem_u32(smg);

    // stage s: A tile at smg + s*2*STG_TILE, B tile right after
    auto load_chunk = [&](int kc, int s) {
        const uint32_t smA = smb + (uint32_t)(s * 2 * STG_TILE) * 2;
        const uint32_t smB = smA + (uint32_t)STG_TILE * 2;
        const __nv_bfloat16* gA = gAb + kc * BK;
        const __nv_bfloat16* gB = gBb + kc * BK;
#pragma unroll
        for (int i = 0; i < 2; i++) {       // A: 128 rows x 4 x 16B = 512 ops
            int idx = i * 256 + tid;
            int r = idx >> 2, c16 = idx & 3;
            CP_ASYNC16(smA + r * (APITCH * 2) + c16 * 16, gA + (size_t)r * K3 + c16 * 8);
        }
#pragma unroll
        for (int i = 0; i < 2; i++) {       // B: 128 rows x 4 x 16B
            int idx = i * 256 + tid;
            int r = idx >> 2, c16 = idx & 3;
            CP_ASYNC16(smB + r * (APITCH * 2) + c16 * 16, gB + (size_t)r * K3 + c16 * 8);
        }
    };

    float acc[4][4][4];
#pragma unroll
    for (int mt = 0; mt < 4; mt++)
#pragma unroll
        for (int nt = 0; nt < 4; nt++)
#pragma unroll
            for (int q = 0; q < 4; q++) acc[mt][nt][q] = 0.f;

    const int NCH = K3 / BK;   // 48
    load_chunk(0, 0); CP_COMMIT();
    load_chunk(1, 1); CP_COMMIT();

    for (int kc = 0; kc < NCH; kc++) {
        CP_WAIT1();            // chunk kc resident
        __syncthreads();
        if (kc + 2 < NCH) load_chunk(kc + 2, (kc + 2) % STAGES);
        CP_COMMIT();

        const int s = kc % STAGES;
        const __nv_bfloat16* As = smg + s * 2 * STG_TILE;
        const __nv_bfloat16* Bs = As + STG_TILE;

#pragma unroll
        for (int ks = 0; ks < 2; ks++) {
            const int kb = ks * 16;
            uint32_t af[4][4], bf[4][2];
#pragma unroll
            for (int mt = 0; mt < 4; mt++) {
                int row = warp_m * 64 + mt * 16 + g;
                const __nv_bfloat16* p0 = As + row * APITCH + kb + 2 * tig;
                const __nv_bfloat16* p1 = As + (row + 8) * APITCH + kb + 2 * tig;
                af[mt][0] = *(const uint32_t*)p0;
                af[mt][1] = *(const uint32_t*)p1;
                af[mt][2] = *(const uint32_t*)(p0 + 8);
                af[mt][3] = *(const uint32_t*)(p1 + 8);
            }
#pragma unroll
            for (int nt = 0; nt < 4; nt++) {
                int col = warp_n * 32 + nt * 8 + g;
                const __nv_bfloat16* p = Bs + col * APITCH + kb + 2 * tig;
                bf[nt][0] = *(const uint32_t*)p;
                bf[nt][1] = *(const uint32_t*)(p + 8);
            }
#pragma unroll
            for (int mt = 0; mt < 4; mt++)
#pragma unroll
                for (int nt = 0; nt < 4; nt++)
                    mma16816(acc[mt][nt], af[mt][0], af[mt][1], af[mt][2], af[mt][3],
                             bf[nt][0], bf[nt][1]);
        }
    }

    // ---- epilogue: direct register -> global with bias ----
#pragma unroll
    for (int mt = 0; mt < 4; mt++) {
        int row0 = br * BMg + warp_m * 64 + mt * 16 + g;
#pragma unroll
        for (int nt = 0; nt < 4; nt++) {
            int col = bc * BNg + warp_n * 32 + nt * 8 + 2 * tig;
            float b0 = bias[col], b1 = bias[col + 1];
            *(float2*)(C + (size_t)row0 * Nout + col) =
                make_float2(acc[mt][nt][0] + b0, acc[mt][nt][1] + b1);
            *(float2*)(C + (size_t)(row0 + 8) * Nout + col) =
                make_float2(acc[mt][nt][2] + b0, acc[mt][nt][3] + b1);
        }
    }
}

// =================================================================
// 64x64 smem matmul helper (unchanged, validated)
// =================================================================
__device__ __forceinline__ void mm64(float* __restrict__ dst,
                                     const float* __restrict__ Am,
                                     const float* __restrict__ Bm,
                                     int tx, int ty, float dscale, float diagadd)
{
    float acc[4][4] = {};
#pragma unroll 8
    for (int k = 0; k < 64; k++) {
        float4 bv = *(const float4*)(Bm + k * LDm + 4 * tx);
        float a0 = Am[(4 * ty + 0) * LDm + k];
        float a1 = Am[(4 * ty + 1) * LDm + k];
        float a2 = Am[(4 * ty + 2) * LDm + k];
        float a3 = Am[(4 * ty + 3) * LDm + k];
        acc[0][0] += a0 * bv.x; acc[0][1] += a0 * bv.y; acc[0][2] += a0 * bv.z; acc[0][3] += a0 * bv.w;
        acc[1][0] += a1 * bv.x; acc[1][1] += a1 * bv.y; acc[1][2] += a1 * bv.z; acc[1][3] += a1 * bv.w;
        acc[2][0] += a2 * bv.x; acc[2][1] += a2 * bv.y; acc[2][2] += a2 * bv.z; acc[2][3] += a2 * bv.w;
        acc[3][0] += a3 * bv.x; acc[3][1] += a3 * bv.y; acc[3][2] += a3 * bv.z; acc[3][3] += a3 * bv.w;
    }
#pragma unroll
    for (int i = 0; i < 4; i++)
#pragma unroll
        for (int j = 0; j < 4; j++) {
            int r = 4 * ty + i, c = 4 * tx + j;
            dst[r * LDm + c] = acc[i][j] * dscale + ((r == c) ? diagadd : 0.f);
        }
    __syncthreads();
}

__device__ __forceinline__ void softmax_rows(float acc[4][4])
{
#pragma unroll
    for (int i = 0; i < 4; i++) {
        float m = fmaxf(fmaxf(acc[i][0], acc[i][1]), fmaxf(acc[i][2], acc[i][3]));
#pragma unroll
        for (int off = 8; off > 0; off >>= 1)
            m = fmaxf(m, __shfl_xor_sync(0xffffffffu, m, off, 16));
        float s = 0.f;
#pragma unroll
        for (int j = 0; j < 4; j++) { acc[i][j] = __expf(acc[i][j] - m); s += acc[i][j]; }
#pragma unroll
        for (int off = 8; off > 0; off >>= 1)
            s += __shfl_xor_sync(0xffffffffu, s, off, 16);
        float inv = 1.f / s;
#pragma unroll
        for (int j = 0; j < 4; j++) acc[i][j] *= inv;
    }
}

// =================================================================
// Temporal attention (unchanged, validated)
// =================================================================
__global__ __launch_bounds__(256, 2) void temporal_attn()
{
    extern __shared__ float smT[];
    float* Q  = smT;
    float* Kt = Q  + 64 * LDm;
    float* V  = Kt + 64 * LDm;
    float* P  = V  + 64 * LDm;
    const int tid = threadIdx.x, tx = tid & 15, ty = tid >> 4;
    const int h = blockIdx.x & 3;
    const int c = (blockIdx.x >> 2) & 63;
    const int b = blockIdx.x >> 8;

    const float* qk = g_qkv + (size_t)b * Ll * M3 + h * 64;
#pragma unroll
    for (int it = 0; it < 16; it++) {
        int idx = it * 256 + tid;
        int nn = idx >> 6, e = idx & 63;
        const float* p = qk + (size_t)(nn * Cc + c) * M3 + e;
        Q [nn * LDm + e]  = p[0];
        Kt[e  * LDm + nn] = p[Dd];
        V [nn * LDm + e]  = p[2 * Dd];
    }
    __syncthreads();

    float acc[4][4] = {};
#pragma unroll 8
    for (int k = 0; k < 64; k++) {
        float4 bv = *(const float4*)(Kt + k * LDm + 4 * tx);
        float a0 = Q[(4 * ty + 0) * LDm + k];
        float a1 = Q[(4 * ty + 1) * LDm + k];
        float a2 = Q[(4 * ty + 2) * LDm + k];
        float a3 = Q[(4 * ty + 3) * LDm + k];
        acc[0][0] += a0 * bv.x; acc[0][1] += a0 * bv.y; acc[0][2] += a0 * bv.z; acc[0][3] += a0 * bv.w;
        acc[1][0] += a1 * bv.x; acc[1][1] += a1 * bv.y; acc[1][2] += a1 * bv.z; acc[1][3] += a1 * bv.w;
        acc[2][0] += a2 * bv.x; acc[2][1] += a2 * bv.y; acc[2][2] += a2 * bv.z; acc[2][3] += a2 * bv.w;
        acc[3][0] += a3 * bv.x; acc[3][1] += a3 * bv.y; acc[3][2] += a3 * bv.z; acc[3][3] += a3 * bv.w;
    }
#pragma unroll
    for (int i = 0; i < 4; i++)
#pragma unroll
        for (int j = 0; j < 4; j++) acc[i][j] *= SCALE_ATT;

    softmax_rows(acc);

#pragma unroll
    for (int i = 0; i < 4; i++)
#pragma unroll
        for (int j = 0; j < 4; j++)
            P[(4 * ty + i) * LDm + 4 * tx + j] = acc[i][j];
    __syncthreads();

    float o[4][4] = {};
#pragma unroll 8
    for (int k = 0; k < 64; k++) {
        float4 bv = *(const float4*)(V + k * LDm + 4 * tx);
        float a0 = P[(4 * ty + 0) * LDm + k];
        float a1 = P[(4 * ty + 1) * LDm + k];
        float a2 = P[(4 * ty + 2) * LDm + k];
        float a3 = P[(4 * ty + 3) * LDm + k];
        o[0][0] += a0 * bv.x; o[0][1] += a0 * bv.y; o[0][2] += a0 * bv.z; o[0][3] += a0 * bv.w;
        o[1][0] += a1 * bv.x; o[1][1] += a1 * bv.y; o[1][2] += a1 * bv.z; o[1][3] += a1 * bv.w;
        o[2][0] += a2 * bv.x; o[2][1] += a2 * bv.y; o[2][2] += a2 * bv.z; o[2][3] += a2 * bv.w;
        o[3][0] += a3 * bv.x; o[3][1] += a3 * bv.y; o[3][2] += a3 * bv.z; o[3][3] += a3 * bv.w;
    }
#pragma unroll
    for (int i = 0; i < 4; i++) {
        size_t l = (size_t)(4 * ty + i) * Cc + c;
        *(float4*)(g_attn + ((size_t)b * Ll + l) * Dd + h * 64 + 4 * tx) =
            make_float4(o[i][0], o[i][1], o[i][2], o[i][3]);
    }
}

// =================================================================
// Spatial branch (unchanged, validated)
// =================================================================
__global__ __launch_bounds__(256, 2) void spatial_riemann(
    const float* __restrict__ x, const float* __restrict__ head_scales)
{
    extern __shared__ float smS[];
    float* B0 = smS;
    float* B1 = B0 + 64 * LDm;
    float* B2 = B1 + 64 * LDm;
    float* B3 = B2 + 64 * LDm;
    float* LM = B3 + 64 * LDm;
    float* red = LM + 64 * LDm;
    __shared__ float s_alpha;

    const int tid = threadIdx.x, tx = tid & 15, ty = tid >> 4;
    const int n = blockIdx.x & 63, b = blockIdx.x >> 6;
    const float* xb = x + ((size_t)b * Ll + n * Cc) * Dd;

    float sacc[4][4] = {};
    for (int kc = 0; kc < 8; kc++) {
#pragma unroll
        for (int it = 0; it < 16; it++) {
            int idx = it * 256 + tid;
            int r = idx >> 6, col = idx & 63;
            float v = xb[(size_t)r * Dd + kc * 64 + col];
            B2[r * LDm + col] = v;
            B3[col * LDm + r] = v;
        }
        __syncthreads();
#pragma unroll 8
        for (int k = 0; k < 64; k++) {
            float4 bv = *(const float4*)(B3 + k * LDm + 4 * tx);
            float a0 = B2[(4 * ty + 0) * LDm + k];
            float a1 = B2[(4 * ty + 1) * LDm + k];
            float a2 = B2[(4 * ty + 2) * LDm + k];
            float a3 = B2[(4 * ty + 3) * LDm + k];
            sacc[0][0] += a0 * bv.x; sacc[0][1] += a0 * bv.y; sacc[0][2] += a0 * bv.z; sacc[0][3] += a0 * bv.w;
            sacc[1][0] += a1 * bv.x; sacc[1][1] += a1 * bv.y; sacc[1][2] += a1 * bv.z; sacc[1][3] += a1 * bv.w;
            sacc[2][0] += a2 * bv.x; sacc[2][1] += a2 * bv.y; sacc[2][2] += a2 * bv.z; sacc[2][3] += a2 * bv.w;
            sacc[3][0] += a3 * bv.x; sacc[3][1] += a3 * bv.y; sacc[3][2] += a3 * bv.z; sacc[3][3] += a3 * bv.w;
        }
        __syncthreads();
    }
#pragma unroll
    for (int i = 0; i < 4; i++)
#pragma unroll
        for (int j = 0; j < 4; j++) {
            int r = 4 * ty + i, c = 4 * tx + j;
            float v = sacc[i][j] * (1.f / (float)Dd);
            if (r == c) v += 1.f + SPD_EPSF;
            B0[r * LDm + c] = v;
        }
    __syncthreads();

    {
        int r = tid >> 2, seg = tid & 3;
        float s = 0.f;
#pragma unroll
        for (int j = 0; j < 16; j++) s += fabsf(B0[r * LDm + seg * 16 + j]);
        red[tid] = s;
    }
    __syncthreads();
    if (tid == 0) {
        float rmax = 0.f;
        for (int r = 0; r < 64; r++)
            rmax = fmaxf(rmax, red[4 * r] + red[4 * r + 1] + red[4 * r + 2] + red[4 * r + 3]);
        s_alpha = 2.f / (1.f + rmax);
    }
    __syncthreads();
    float alpha = s_alpha;

#pragma unroll
    for (int i = 0; i < 4; i++)
#pragma unroll
        for (int j = 0; j < 4; j++) {
            int r = 4 * ty + i, c = 4 * tx + j;
            B1[r * LDm + c] = (r == c) ? alpha : 0.f;
        }
    __syncthreads();

    for (int it = 0; it < 6; it++) {
        mm64(B2, B0, B1, tx, ty, 1.f, 0.f);
        mm64(B3, B1, B2, tx, ty, 1.f, 0.f);
#pragma unroll
        for (int i = 0; i < 4; i++)
#pragma unroll
            for (int j = 0; j < 4; j++) {
                int r = 4 * ty + i, c = 4 * tx + j;
                B1[r * LDm + c] = 2.f * B1[r * LDm + c] - B3[r * LDm + c];
            }
        __syncthreads();
    }

#pragma unroll
    for (int i = 0; i < 4; i++)
#pragma unroll
        for (int j = 0; j < 4; j++) {
            int r = 4 * ty + i, c = 4 * tx + j;
            B2[r * LDm + c] = ((r == c) ? 1.f : 0.f) - 2.f * B1[r * LDm + c];
        }
    __syncthreads();

    mm64(B0, B2, B2, tx, ty, 1.f, 0.f);

#pragma unroll
    for (int i = 0; i < 4; i++)
#pragma unroll
        for (int j = 0; j < 4; j++) {
            int r = 4 * ty + i, c = 4 * tx + j;
            B3[r * LDm + c] = (r == c) ? (1.f / 19.f) : 0.f;
        }
    __syncthreads();
    {
        float* cur = B3; float* oth = B1;
        for (int m = 8; m >= 0; m--) {
            mm64(oth, cur, B0, tx, ty, 1.f, 1.f / (float)(2 * m + 1));
            float* t = cur; cur = oth; oth = t;
        }
        mm64(LM, B2, cur, tx, ty, 2.f, 0.f);
    }

    const float* qk = g_qkv + (size_t)b * Ll * M3 + H2d * 64;
    for (int h = 0; h < H2d; h++) {
        float hs = head_scales[h];
#pragma unroll
        for (int it = 0; it < 16; it++) {
            int idx = it * 256 + tid;
            int r = idx >> 6, e = idx & 63;
            const float* p = qk + (size_t)(n * Cc + r) * M3 + h * 64 + e;
            B0[r * LDm + e] = p[0];
            B2[e * LDm + r] = p[Dd];
            B3[r * LDm + e] = p[2 * Dd];
        }
        __syncthreads();

        float a4[4][4] = {};
#pragma unroll 8
        for (int k = 0; k < 64; k++) {
            float4 bv = *(const float4*)(B2 + k * LDm + 4 * tx);
            float a0 = B0[(4 * ty + 0) * LDm + k];
            float a1 = B0[(4 * ty + 1) * LDm + k];
            float a2 = B0[(4 * ty + 2) * LDm + k];
            float a3 = B0[(4 * ty + 3) * LDm + k];
            a4[0][0] += a0 * bv.x; a4[0][1] += a0 * bv.y; a4[0][2] += a0 * bv.z; a4[0][3] += a0 * bv.w;
            a4[1][0] += a1 * bv.x; a4[1][1] += a1 * bv.y; a4[1][2] += a1 * bv.z; a4[1][3] += a1 * bv.w;
            a4[2][0] += a2 * bv.x; a4[2][1] += a2 * bv.y; a4[2][2] += a2 * bv.z; a4[2][3] += a2 * bv.w;
            a4[3][0] += a3 * bv.x; a4[3][1] += a3 * bv.y; a4[3][2] += a3 * bv.z; a4[3][3] += a3 * bv.w;
        }
#pragma unroll
        for (int i = 0; i < 4; i++)
#pragma unroll
            for (int j = 0; j < 4; j++)
                a4[i][j] = a4[i][j] * SCALE_ATT + hs * LM[(4 * ty + i) * LDm + 4 * tx + j];

        softmax_rows(a4);

#pragma unroll
        for (int i = 0; i < 4; i++)
#pragma unroll
            for (int j = 0; j < 4; j++)
                B1[(4 * ty + i) * LDm + 4 * tx + j] = a4[i][j];
        __syncthreads();

        float o[4][4] = {};
#pragma unroll 8
        for (int k = 0; k < 64; k++) {
            float4 bv = *(const float4*)(B3 + k * LDm + 4 * tx);
            float a0 = B1[(4 * ty + 0) * LDm + k];
            float a1 = B1[(4 * ty + 1) * LDm + k];
            float a2 = B1[(4 * ty + 2) * LDm + k];
            float a3 = B1[(4 * ty + 3) * LDm + k];
            o[0][0] += a0 * bv.x; o[0][1] += a0 * bv.y; o[0][2] += a0 * bv.z; o[0][3] += a0 * bv.w;
            o[1][0] += a1 * bv.x; o[1][1] += a1 * bv.y; o[1][2] += a1 * bv.z; o[1][3] += a1 * bv.w;
            o[2][0] += a2 * bv.x; o[2][1] += a2 * bv.y; o[2][2] += a2 * bv.z; o[2][3] += a2 * bv.w;
            o[3][0] += a3 * bv.x; o[3][1] += a3 * bv.y; o[3][2] += a3 * bv.z; o[3][3] += a3 * bv.w;
        }
#pragma unroll
        for (int i = 0; i < 4; i++) {
            size_t l = (size_t)n * Cc + 4 * ty + i;
            *(float4*)(g_attn + ((size_t)b * Ll + l) * Dd + (H2d + h) * 64 + 4 * tx) =
                make_float4(o[i][0], o[i][1], o[i][2], o[i][3]);
        }
        __syncthreads();
    }
}

// =================================================================
// launch
// =================================================================
extern "C" void kernel_launch(void* const* d_in, const int* in_sizes, int n_in,
                              void* d_out, int out_size)
{
    const float* x     = (const float*)d_in[0];
    const float* qkv_w = (const float*)d_in[1];
    const float* qkv_b = (const float*)d_in[2];
    const float* fc_w  = (const float*)d_in[3];
    const float* fc_b  = (const float*)d_in[4];
    const float* hsc   = (const float*)d_in[5];
    float* out = (float*)d_out;

    float* p_qkv = nullptr;
    float* p_attn = nullptr;
    __nv_bfloat16* p_abuf = nullptr;
    __nv_bfloat16* p_wbuf = nullptr;
    cudaGetSymbolAddress((void**)&p_qkv, g_qkv);
    cudaGetSymbolAddress((void**)&p_attn, g_attn);
    cudaGetSymbolAddress((void**)&p_abuf, g_abuf);
    cudaGetSymbolAddress((void**)&p_wbuf, g_wbuf);

    const int smemT = 4 * 64 * LDm * (int)sizeof(float);
    const int smemS = 5 * 64 * LDm * (int)sizeof(float) + 256 * 4;
    const int smemG = STAGES * 2 * STG_TILE * (int)sizeof(__nv_bfloat16);   // 61440
    cudaFuncSetAttribute(temporal_attn, cudaFuncAttributeMaxDynamicSharedMemorySize, smemT);
    cudaFuncSetAttribute(spatial_riemann, cudaFuncAttributeMaxDynamicSharedMemorySize, smemS);
    cudaFuncSetAttribute(gemm_mma, cudaFuncAttributeMaxDynamicSharedMemorySize, smemG);

    // 1) split x and qkv_w to bf16x3
    {
        size_t tot = (size_t)MROWS * Dd;
        conv_split<<<(unsigned)(tot / 512), 256>>>(x, p_abuf, tot, 0);
        size_t totw = (size_t)M3 * Dd;
        conv_split<<<(unsigned)(totw / 512), 256>>>(qkv_w, p_wbuf, totw, 1);
    }
    // 2) QKV projection via mma.sync bf16x3
    {
        dim3 grid(M3 / BNg, MROWS / BMg);   // (12, 512)
        gemm_mma<<<grid, 256, smemG>>>(p_abuf, p_wbuf, qkv_b, p_qkv, M3);
    }
    // 3) temporal heads
    temporal_attn<<<Bsz * Cc * H2d, 256, smemT>>>();
    // 4) SPD log bias + spatial heads
    spatial_riemann<<<Bsz * Nn, 256, smemS>>>(x, hsc);
    // 5) split attn output and fc_w to bf16x3
    {
        size_t tot = (size_t)MROWS * Dd;
        conv_split<<<(unsigned)(tot / 512), 256>>>(p_attn, p_abuf, tot, 0);
        size_t totw = (size_t)Dd * Dd;
        conv_split<<<(unsigned)(totw / 512), 256>>>(fc_w, p_wbuf, totw, 1);
    }
    // 6) output projection via mma.sync bf16x3
    {
        dim3 grid(Dd / BNg, MROWS / BMg);   // (4, 512)
        gemm_mma<<<grid, 256, smemG>>>(p_abuf, p_wbuf, fc_b, out, Dd);
    }
}

// round 7
// speedup vs baseline: 1.8761x; 1.1295x over previous
#include <cuda_runtime.h>
#include <cuda_bf16.h>
#include <cstdint>
#include <cstddef>
#include <math.h>

#define H2d 4
#define Bsz 16
#define Cc 64
#define Nn 64
#define Dd 512
#define Ll (Nn*Cc)            // 4096
#define M3 (3*Dd)             // 1536
#define LDm 68                // padded smem leading dim (floats)
#define SCALE_ATT 0.125f      // 1/sqrt(64)
#define SPD_EPSF 1e-5f

#define MROWS (Bsz*Ll)        // 65536
#define K2 1024               // stored: [hi(512) | lo(512)]
#define NCH 48                // compute chunks: 3 phases x 16 chunks of 32
#define BK 32                 // bf16 K per chunk
#define BMg 128
#define BNg 128
#define APITCH 40             // bf16 units per smem row (32 + 8 pad) -> 80B pitch
#define STG_TILE (128*APITCH) // bf16 elems per tile per stage
#define STAGES 3

// ---------------- scratch (static device memory; no allocations) ----------------
__device__ float g_qkv[(size_t)Bsz * Ll * M3];            // (B, L, 1536) fp32
__device__ float g_attn[(size_t)Bsz * Ll * Dd];           // (B, L, 512)  fp32
__device__ __nv_bfloat16 g_abuf[(size_t)MROWS * K2];      // bf16 hi|lo activations
__device__ __nv_bfloat16 g_wbuf[(size_t)M3 * K2];         // bf16 hi|lo weights

// =================================================================
// PTX helpers (plain PTX only: cp.async + mma.sync + ldmatrix)
// =================================================================
__device__ __forceinline__ uint32_t smem_u32(const void* p) {
    uint32_t a;
    asm("{ .reg .u64 t; cvta.to.shared.u64 t, %1; cvt.u32.u64 %0, t; }" : "=r"(a) : "l"(p));
    return a;
}
#define CP_ASYNC16(dst, src) \
    asm volatile("cp.async.cg.shared.global [%0], [%1], 16;" :: "r"(dst), "l"(src))
#define CP_COMMIT() asm volatile("cp.async.commit_group;" ::: "memory")
#define CP_WAIT1()  asm volatile("cp.async.wait_group 1;" ::: "memory")

__device__ __forceinline__ void ldsm_x4(uint32_t& r0, uint32_t& r1, uint32_t& r2,
                                        uint32_t& r3, uint32_t addr) {
    asm volatile("ldmatrix.sync.aligned.m8n8.x4.shared.b16 {%0,%1,%2,%3}, [%4];"
                 : "=r"(r0), "=r"(r1), "=r"(r2), "=r"(r3) : "r"(addr));
}
__device__ __forceinline__ void mma16816(float c[4], uint32_t a0, uint32_t a1,
                                         uint32_t a2, uint32_t a3,
                                         uint32_t b0, uint32_t b1) {
    asm volatile(
        "mma.sync.aligned.m16n8k16.row.col.f32.bf16.bf16.f32 "
        "{%0,%1,%2,%3}, {%4,%5,%6,%7}, {%8,%9}, {%0,%1,%2,%3};"
        : "+f"(c[0]), "+f"(c[1]), "+f"(c[2]), "+f"(c[3])
        : "r"(a0), "r"(a1), "r"(a2), "r"(a3), "r"(b0), "r"(b1));
}

// =================================================================
// fp32 -> bf16 hi|lo split. dst: [rows][1024] = [hi 512 | lo 512]
// =================================================================
__global__ void conv_split(const float* __restrict__ src, __nv_bfloat16* __restrict__ dst,
                           size_t total)
{
    size_t i = (size_t)blockIdx.x * blockDim.x + threadIdx.x;
    size_t e = i * 2;
    if (e >= total) return;
    size_t m = e >> 9;          // /512
    int k = (int)(e & 511);
    float2 v = *(const float2*)(src + e);
    __nv_bfloat16 h0 = __float2bfloat16(v.x);
    __nv_bfloat16 h1 = __float2bfloat16(v.y);
    __nv_bfloat16 l0 = __float2bfloat16(v.x - __bfloat162float(h0));
    __nv_bfloat16 l1 = __float2bfloat16(v.y - __bfloat162float(h1));
    __nv_bfloat162 hh; hh.x = h0; hh.y = h1;
    __nv_bfloat162 ll; ll.x = l0; ll.y = l1;
    __nv_bfloat16* base = dst + m * K2 + k;
    *(__nv_bfloat162*)(base)       = hh;
    *(__nv_bfloat162*)(base + 512) = ll;
}

// =================================================================
// mma.sync bf16x3 GEMM: C = A @ W^T + bias, fp32-accurate via
// 3 K-phases over [hi|lo] storage: hi*hi + lo*hi + hi*lo.
// 128x128 CTA tile, 8 warps of 64x32, BK=32, 3-stage cp.async, ldmatrix.
// =================================================================
__global__ __launch_bounds__(256) void gemm_mma(
    const __nv_bfloat16* __restrict__ A, const __nv_bfloat16* __restrict__ W,
    const float* __restrict__ bias, float* __restrict__ C, int Nout)
{
    extern __shared__ __nv_bfloat16 smg[];
    const int tid = threadIdx.x;
    const int wid = tid >> 5, lane = tid & 31;
    const int g = lane >> 2, tig = lane & 3;
    const int warp_m = wid >> 2, warp_n = wid & 3;     // 2 x 4 warps
    const int bc = blockIdx.x, br = blockIdx.y;

    const __nv_bfloat16* gAb = A + (size_t)(br * BMg) * K2;
    const __nv_bfloat16* gBb = W + (size_t)(bc * BNg) * K2;

    const uint32_t smb = smem_u32(smg);

    // per-chunk segment offsets: phase 0: hiA*hiW, 1: loA*hiW, 2: hiA*loW
    auto load_chunk = [&](int kc, int s) {
        const int phase = kc >> 4, k16 = kc & 15;
        const int aoff = ((phase == 1) ? 512 : 0) + k16 * BK;
        const int boff = ((phase == 2) ? 512 : 0) + k16 * BK;
        const uint32_t smA = smb + (uint32_t)(s * 2 * STG_TILE) * 2;
        const uint32_t smB = smA + (uint32_t)STG_TILE * 2;
        const __nv_bfloat16* gA = gAb + aoff;
        const __nv_bfloat16* gB = gBb + boff;
#pragma unroll
        for (int i = 0; i < 2; i++) {       // A: 128 rows x 4 x 16B
            int idx = i * 256 + tid;
            int r = idx >> 2, c16 = idx & 3;
            CP_ASYNC16(smA + r * (APITCH * 2) + c16 * 16, gA + (size_t)r * K2 + c16 * 8);
        }
#pragma unroll
        for (int i = 0; i < 2; i++) {       // B: 128 rows x 4 x 16B
            int idx = i * 256 + tid;
            int r = idx >> 2, c16 = idx & 3;
            CP_ASYNC16(smB + r * (APITCH * 2) + c16 * 16, gB + (size_t)r * K2 + c16 * 8);
        }
    };

    float acc[4][4][4];
#pragma unroll
    for (int mt = 0; mt < 4; mt++)
#pragma unroll
        for (int nt = 0; nt < 4; nt++)
#pragma unroll
            for (int q = 0; q < 4; q++) acc[mt][nt][q] = 0.f;

    // ldmatrix lane address components
    const int a_row = warp_m * 64 + (lane & 15);       // + mt*16
    const int a_kof = (lane >> 4) * 8;                 // + ks*16
    const int b_col = warp_n * 32 + (lane & 7) + ((lane >> 4) << 3);  // + ntp*16
    const int b_kof = ((lane >> 3) & 1) * 8;           // + ks*16

    load_chunk(0, 0); CP_COMMIT();
    load_chunk(1, 1); CP_COMMIT();

    for (int kc = 0; kc < NCH; kc++) {
        CP_WAIT1();            // chunk kc resident
        __syncthreads();
        if (kc + 2 < NCH) load_chunk(kc + 2, (kc + 2) % STAGES);
        CP_COMMIT();

        const int s = kc % STAGES;
        const uint32_t smA = smb + (uint32_t)(s * 2 * STG_TILE) * 2;
        const uint32_t smB = smA + (uint32_t)STG_TILE * 2;

#pragma unroll
        for (int ks = 0; ks < 2; ks++) {
            const int kb = ks * 16;
            uint32_t af[4][4], bf[2][4];
#pragma unroll
            for (int mt = 0; mt < 4; mt++) {
                uint32_t addr = smA + (uint32_t)(((a_row + mt * 16) * APITCH) + kb + a_kof) * 2;
                ldsm_x4(af[mt][0], af[mt][1], af[mt][2], af[mt][3], addr);
            }
#pragma unroll
            for (int ntp = 0; ntp < 2; ntp++) {
                uint32_t addr = smB + (uint32_t)(((b_col + ntp * 16) * APITCH) + kb + b_kof) * 2;
                ldsm_x4(bf[ntp][0], bf[ntp][1], bf[ntp][2], bf[ntp][3], addr);
            }
#pragma unroll
            for (int mt = 0; mt < 4; mt++)
#pragma unroll
                for (int ntp = 0; ntp < 2; ntp++) {
                    mma16816(acc[mt][2 * ntp],     af[mt][0], af[mt][1], af[mt][2], af[mt][3],
                             bf[ntp][0], bf[ntp][1]);
                    mma16816(acc[mt][2 * ntp + 1], af[mt][0], af[mt][1], af[mt][2], af[mt][3],
                             bf[ntp][2], bf[ntp][3]);
                }
        }
    }

    // ---- epilogue: direct register -> global with bias ----
#pragma unroll
    for (int mt = 0; mt < 4; mt++) {
        int row0 = br * BMg + warp_m * 64 + mt * 16 + g;
#pragma unroll
        for (int nt = 0; nt < 4; nt++) {
            int col = bc * BNg + warp_n * 32 + nt * 8 + 2 * tig;
            float b0 = bias[col], b1 = bias[col + 1];
            *(float2*)(C + (size_t)row0 * Nout + col) =
                make_float2(acc[mt][nt][0] + b0, acc[mt][nt][1] + b1);
            *(float2*)(C + (size_t)(row0 + 8) * Nout + col) =
                make_float2(acc[mt][nt][2] + b0, acc[mt][nt][3] + b1);
        }
    }
}

// =================================================================
// 64x64 smem matmul helper (validated)
// =================================================================
__device__ __forceinline__ void mm64(float* __restrict__ dst,
                                     const float* __restrict__ Am,
                                     const float* __restrict__ Bm,
                                     int tx, int ty, float dscale, float diagadd)
{
    float acc[4][4] = {};
#pragma unroll 8
    for (int k = 0; k < 64; k++) {
        float4 bv = *(const float4*)(Bm + k * LDm + 4 * tx);
        float a0 = Am[(4 * ty + 0) * LDm + k];
        float a1 = Am[(4 * ty + 1) * LDm + k];
        float a2 = Am[(4 * ty + 2) * LDm + k];
        float a3 = Am[(4 * ty + 3) * LDm + k];
        acc[0][0] += a0 * bv.x; acc[0][1] += a0 * bv.y; acc[0][2] += a0 * bv.z; acc[0][3] += a0 * bv.w;
        acc[1][0] += a1 * bv.x; acc[1][1] += a1 * bv.y; acc[1][2] += a1 * bv.z; acc[1][3] += a1 * bv.w;
        acc[2][0] += a2 * bv.x; acc[2][1] += a2 * bv.y; acc[2][2] += a2 * bv.z; acc[2][3] += a2 * bv.w;
        acc[3][0] += a3 * bv.x; acc[3][1] += a3 * bv.y; acc[3][2] += a3 * bv.z; acc[3][3] += a3 * bv.w;
    }
#pragma unroll
    for (int i = 0; i < 4; i++)
#pragma unroll
        for (int j = 0; j < 4; j++) {
            int r = 4 * ty + i, c = 4 * tx + j;
            dst[r * LDm + c] = acc[i][j] * dscale + ((r == c) ? diagadd : 0.f);
        }
    __syncthreads();
}

__device__ __forceinline__ void softmax_rows(float acc[4][4])
{
#pragma unroll
    for (int i = 0; i < 4; i++) {
        float m = fmaxf(fmaxf(acc[i][0], acc[i][1]), fmaxf(acc[i][2], acc[i][3]));
#pragma unroll
        for (int off = 8; off > 0; off >>= 1)
            m = fmaxf(m, __shfl_xor_sync(0xffffffffu, m, off, 16));
        float s = 0.f;
#pragma unroll
        for (int j = 0; j < 4; j++) { acc[i][j] = __expf(acc[i][j] - m); s += acc[i][j]; }
#pragma unroll
        for (int off = 8; off > 0; off >>= 1)
            s += __shfl_xor_sync(0xffffffffu, s, off, 16);
        float inv = 1.f / s;
#pragma unroll
        for (int j = 0; j < 4; j++) acc[i][j] *= inv;
    }
}

// =================================================================
// Temporal attention (unchanged, validated)
// =================================================================
__global__ __launch_bounds__(256, 2) void temporal_attn()
{
    extern __shared__ float smT[];
    float* Q  = smT;
    float* Kt = Q  + 64 * LDm;
    float* V  = Kt + 64 * LDm;
    float* P  = V  + 64 * LDm;
    const int tid = threadIdx.x, tx = tid & 15, ty = tid >> 4;
    const int h = blockIdx.x & 3;
    const int c = (blockIdx.x >> 2) & 63;
    const int b = blockIdx.x >> 8;

    const float* qk = g_qkv + (size_t)b * Ll * M3 + h * 64;
#pragma unroll
    for (int it = 0; it < 16; it++) {
        int idx = it * 256 + tid;
        int nn = idx >> 6, e = idx & 63;
        const float* p = qk + (size_t)(nn * Cc + c) * M3 + e;
        Q [nn * LDm + e]  = p[0];
        Kt[e  * LDm + nn] = p[Dd];
        V [nn * LDm + e]  = p[2 * Dd];
    }
    __syncthreads();

    float acc[4][4] = {};
#pragma unroll 8
    for (int k = 0; k < 64; k++) {
        float4 bv = *(const float4*)(Kt + k * LDm + 4 * tx);
        float a0 = Q[(4 * ty + 0) * LDm + k];
        float a1 = Q[(4 * ty + 1) * LDm + k];
        float a2 = Q[(4 * ty + 2) * LDm + k];
        float a3 = Q[(4 * ty + 3) * LDm + k];
        acc[0][0] += a0 * bv.x; acc[0][1] += a0 * bv.y; acc[0][2] += a0 * bv.z; acc[0][3] += a0 * bv.w;
        acc[1][0] += a1 * bv.x; acc[1][1] += a1 * bv.y; acc[1][2] += a1 * bv.z; acc[1][3] += a1 * bv.w;
        acc[2][0] += a2 * bv.x; acc[2][1] += a2 * bv.y; acc[2][2] += a2 * bv.z; acc[2][3] += a2 * bv.w;
        acc[3][0] += a3 * bv.x; acc[3][1] += a3 * bv.y; acc[3][2] += a3 * bv.z; acc[3][3] += a3 * bv.w;
    }
#pragma unroll
    for (int i = 0; i < 4; i++)
#pragma unroll
        for (int j = 0; j < 4; j++) acc[i][j] *= SCALE_ATT;

    softmax_rows(acc);

#pragma unroll
    for (int i = 0; i < 4; i++)
#pragma unroll
        for (int j = 0; j < 4; j++)
            P[(4 * ty + i) * LDm + 4 * tx + j] = acc[i][j];
    __syncthreads();

    float o[4][4] = {};
#pragma unroll 8
    for (int k = 0; k < 64; k++) {
        float4 bv = *(const float4*)(V + k * LDm + 4 * tx);
        float a0 = P[(4 * ty + 0) * LDm + k];
        float a1 = P[(4 * ty + 1) * LDm + k];
        float a2 = P[(4 * ty + 2) * LDm + k];
        float a3 = P[(4 * ty + 3) * LDm + k];
        o[0][0] += a0 * bv.x; o[0][1] += a0 * bv.y; o[0][2] += a0 * bv.z; o[0][3] += a0 * bv.w;
        o[1][0] += a1 * bv.x; o[1][1] += a1 * bv.y; o[1][2] += a1 * bv.z; o[1][3] += a1 * bv.w;
        o[2][0] += a2 * bv.x; o[2][1] += a2 * bv.y; o[2][2] += a2 * bv.z; o[2][3] += a2 * bv.w;
        o[3][0] += a3 * bv.x; o[3][1] += a3 * bv.y; o[3][2] += a3 * bv.z; o[3][3] += a3 * bv.w;
    }
#pragma unroll
    for (int i = 0; i < 4; i++) {
        size_t l = (size_t)(4 * ty + i) * Cc + c;
        *(float4*)(g_attn + ((size_t)b * Ll + l) * Dd + h * 64 + 4 * tx) =
            make_float4(o[i][0], o[i][1], o[i][2], o[i][3]);
    }
}

// =================================================================
// Spatial branch: NS 5 iters, Gregory 6 terms (error budget analysis
// in commit log: |z|<=0.5 -> truncation ~2e-5 abs, x0.1 head scale)
// =================================================================
__global__ __launch_bounds__(256, 2) void spatial_riemann(
    const float* __restrict__ x, const float* __restrict__ head_scales)
{
    extern __shared__ float smS[];
    float* B0 = smS;
    float* B1 = B0 + 64 * LDm;
    float* B2 = B1 + 64 * LDm;
    float* B3 = B2 + 64 * LDm;
    float* LM = B3 + 64 * LDm;
    float* red = LM + 64 * LDm;
    __shared__ float s_alpha;

    const int tid = threadIdx.x, tx = tid & 15, ty = tid >> 4;
    const int n = blockIdx.x & 63, b = blockIdx.x >> 6;
    const float* xb = x + ((size_t)b * Ll + n * Cc) * Dd;

    float sacc[4][4] = {};
    for (int kc = 0; kc < 8; kc++) {
#pragma unroll
        for (int it = 0; it < 16; it++) {
            int idx = it * 256 + tid;
            int r = idx >> 6, col = idx & 63;
            float v = xb[(size_t)r * Dd + kc * 64 + col];
            B2[r * LDm + col] = v;
            B3[col * LDm + r] = v;
        }
        __syncthreads();
#pragma unroll 8
        for (int k = 0; k < 64; k++) {
            float4 bv = *(const float4*)(B3 + k * LDm + 4 * tx);
            float a0 = B2[(4 * ty + 0) * LDm + k];
            float a1 = B2[(4 * ty + 1) * LDm + k];
            float a2 = B2[(4 * ty + 2) * LDm + k];
            float a3 = B2[(4 * ty + 3) * LDm + k];
            sacc[0][0] += a0 * bv.x; sacc[0][1] += a0 * bv.y; sacc[0][2] += a0 * bv.z; sacc[0][3] += a0 * bv.w;
            sacc[1][0] += a1 * bv.x; sacc[1][1] += a1 * bv.y; sacc[1][2] += a1 * bv.z; sacc[1][3] += a1 * bv.w;
            sacc[2][0] += a2 * bv.x; sacc[2][1] += a2 * bv.y; sacc[2][2] += a2 * bv.z; sacc[2][3] += a2 * bv.w;
            sacc[3][0] += a3 * bv.x; sacc[3][1] += a3 * bv.y; sacc[3][2] += a3 * bv.z; sacc[3][3] += a3 * bv.w;
        }
        __syncthreads();
    }
#pragma unroll
    for (int i = 0; i < 4; i++)
#pragma unroll
        for (int j = 0; j < 4; j++) {
            int r = 4 * ty + i, c = 4 * tx + j;
            float v = sacc[i][j] * (1.f / (float)Dd);
            if (r == c) v += 1.f + SPD_EPSF;
            B0[r * LDm + c] = v;
        }
    __syncthreads();

    {
        int r = tid >> 2, seg = tid & 3;
        float s = 0.f;
#pragma unroll
        for (int j = 0; j < 16; j++) s += fabsf(B0[r * LDm + seg * 16 + j]);
        red[tid] = s;
    }
    __syncthreads();
    if (tid == 0) {
        float rmax = 0.f;
        for (int r = 0; r < 64; r++)
            rmax = fmaxf(rmax, red[4 * r] + red[4 * r + 1] + red[4 * r + 2] + red[4 * r + 3]);
        s_alpha = 2.f / (1.f + rmax);
    }
    __syncthreads();
    float alpha = s_alpha;

#pragma unroll
    for (int i = 0; i < 4; i++)
#pragma unroll
        for (int j = 0; j < 4; j++) {
            int r = 4 * ty + i, c = 4 * tx + j;
            B1[r * LDm + c] = (r == c) ? alpha : 0.f;
        }
    __syncthreads();

    // Newton-Schulz: 5 iterations (residual 0.5^32 << fp32 eps)
    for (int it = 0; it < 5; it++) {
        mm64(B2, B0, B1, tx, ty, 1.f, 0.f);
        mm64(B3, B1, B2, tx, ty, 1.f, 0.f);
#pragma unroll
        for (int i = 0; i < 4; i++)
#pragma unroll
            for (int j = 0; j < 4; j++) {
                int r = 4 * ty + i, c = 4 * tx + j;
                B1[r * LDm + c] = 2.f * B1[r * LDm + c] - B3[r * LDm + c];
            }
        __syncthreads();
    }

#pragma unroll
    for (int i = 0; i < 4; i++)
#pragma unroll
        for (int j = 0; j < 4; j++) {
            int r = 4 * ty + i, c = 4 * tx + j;
            B2[r * LDm + c] = ((r == c) ? 1.f : 0.f) - 2.f * B1[r * LDm + c];
        }
    __syncthreads();

    mm64(B0, B2, B2, tx, ty, 1.f, 0.f);   // W = Z^2

    // Gregory 6 terms: P = sum_{m=0}^{5} W^m/(2m+1), Horner
#pragma unroll
    for (int i = 0; i < 4; i++)
#pragma unroll
        for (int j = 0; j < 4; j++) {
            int r = 4 * ty + i, c = 4 * tx + j;
            B3[r * LDm + c] = (r == c) ? (1.f / 11.f) : 0.f;
        }
    __syncthreads();
    {
        float* cur = B3; float* oth = B1;
        for (int m = 4; m >= 0; m--) {
            mm64(oth, cur, B0, tx, ty, 1.f, 1.f / (float)(2 * m + 1));
            float* t = cur; cur = oth; oth = t;
        }
        mm64(LM, B2, cur, tx, ty, 2.f, 0.f);   // Lm = 2 Z P
    }

    const float* qk = g_qkv + (size_t)b * Ll * M3 + H2d * 64;
    for (int h = 0; h < H2d; h++) {
        float hs = head_scales[h];
#pragma unroll
        for (int it = 0; it < 16; it++) {
            int idx = it * 256 + tid;
            int r = idx >> 6, e = idx & 63;
            const float* p = qk + (size_t)(n * Cc + r) * M3 + h * 64 + e;
            B0[r * LDm + e] = p[0];
            B2[e * LDm + r] = p[Dd];
            B3[r * LDm + e] = p[2 * Dd];
        }
        __syncthreads();

        float a4[4][4] = {};
#pragma unroll 8
        for (int k = 0; k < 64; k++) {
            float4 bv = *(const float4*)(B2 + k * LDm + 4 * tx);
            float a0 = B0[(4 * ty + 0) * LDm + k];
            float a1 = B0[(4 * ty + 1) * LDm + k];
            float a2 = B0[(4 * ty + 2) * LDm + k];
            float a3 = B0[(4 * ty + 3) * LDm + k];
            a4[0][0] += a0 * bv.x; a4[0][1] += a0 * bv.y; a4[0][2] += a0 * bv.z; a4[0][3] += a0 * bv.w;
            a4[1][0] += a1 * bv.x; a4[1][1] += a1 * bv.y; a4[1][2] += a1 * bv.z; a4[1][3] += a1 * bv.w;
            a4[2][0] += a2 * bv.x; a4[2][1] += a2 * bv.y; a4[2][2] += a2 * bv.z; a4[2][3] += a2 * bv.w;
            a4[3][0] += a3 * bv.x; a4[3][1] += a3 * bv.y; a4[3][2] += a3 * bv.z; a4[3][3] += a3 * bv.w;
        }
#pragma unroll
        for (int i = 0; i < 4; i++)
#pragma unroll
            for (int j = 0; j < 4; j++)
                a4[i][j] = a4[i][j] * SCALE_ATT + hs * LM[(4 * ty + i) * LDm + 4 * tx + j];

        softmax_rows(a4);

#pragma unroll
        for (int i = 0; i < 4; i++)
#pragma unroll
            for (int j = 0; j < 4; j++)
                B1[(4 * ty + i) * LDm + 4 * tx + j] = a4[i][j];
        __syncthreads();

        float o[4][4] = {};
#pragma unroll 8
        for (int k = 0; k < 64; k++) {
            float4 bv = *(const float4*)(B3 + k * LDm + 4 * tx);
            float a0 = B1[(4 * ty + 0) * LDm + k];
            float a1 = B1[(4 * ty + 1) * LDm + k];
            float a2 = B1[(4 * ty + 2) * LDm + k];
            float a3 = B1[(4 * ty + 3) * LDm + k];
            o[0][0] += a0 * bv.x; o[0][1] += a0 * bv.y; o[0][2] += a0 * bv.z; o[0][3] += a0 * bv.w;
            o[1][0] += a1 * bv.x; o[1][1] += a1 * bv.y; o[1][2] += a1 * bv.z; o[1][3] += a1 * bv.w;
            o[2][0] += a2 * bv.x; o[2][1] += a2 * bv.y; o[2][2] += a2 * bv.z; o[2][3] += a2 * bv.w;
            o[3][0] += a3 * bv.x; o[3][1] += a3 * bv.y; o[3][2] += a3 * bv.z; o[3][3] += a3 * bv.w;
        }
#pragma unroll
        for (int i = 0; i < 4; i++) {
            size_t l = (size_t)n * Cc + 4 * ty + i;
            *(float4*)(g_attn + ((size_t)b * Ll + l) * Dd + (H2d + h) * 64 + 4 * tx) =
                make_float4(o[i][0], o[i][1], o[i][2], o[i][3]);
        }
        __syncthreads();
    }
}

// =================================================================
// launch
// =================================================================
extern "C" void kernel_launch(void* const* d_in, const int* in_sizes, int n_in,
                              void* d_out, int out_size)
{
    const float* x     = (const float*)d_in[0];
    const float* qkv_w = (const float*)d_in[1];
    const float* qkv_b = (const float*)d_in[2];
    const float* fc_w  = (const float*)d_in[3];
    const float* fc_b  = (const float*)d_in[4];
    const float* hsc   = (const float*)d_in[5];
    float* out = (float*)d_out;

    float* p_qkv = nullptr;
    float* p_attn = nullptr;
    __nv_bfloat16* p_abuf = nullptr;
    __nv_bfloat16* p_wbuf = nullptr;
    cudaGetSymbolAddress((void**)&p_qkv, g_qkv);
    cudaGetSymbolAddress((void**)&p_attn, g_attn);
    cudaGetSymbolAddress((void**)&p_abuf, g_abuf);
    cudaGetSymbolAddress((void**)&p_wbuf, g_wbuf);

    const int smemT = 4 * 64 * LDm * (int)sizeof(float);
    const int smemS = 5 * 64 * LDm * (int)sizeof(float) + 256 * 4;
    const int smemG = STAGES * 2 * STG_TILE * (int)sizeof(__nv_bfloat16);   // 61440
    cudaFuncSetAttribute(temporal_attn, cudaFuncAttributeMaxDynamicSharedMemorySize, smemT);
    cudaFuncSetAttribute(spatial_riemann, cudaFuncAttributeMaxDynamicSharedMemorySize, smemS);
    cudaFuncSetAttribute(gemm_mma, cudaFuncAttributeMaxDynamicSharedMemorySize, smemG);

    // 1) split x and qkv_w to bf16 hi|lo
    {
        size_t tot = (size_t)MROWS * Dd;
        conv_split<<<(unsigned)(tot / 512), 256>>>(x, p_abuf, tot);
        size_t totw = (size_t)M3 * Dd;
        conv_split<<<(unsigned)(totw / 512), 256>>>(qkv_w, p_wbuf, totw);
    }
    // 2) QKV projection via mma.sync bf16x3
    {
        dim3 grid(M3 / BNg, MROWS / BMg);   // (12, 512)
        gemm_mma<<<grid, 256, smemG>>>(p_abuf, p_wbuf, qkv_b, p_qkv, M3);
    }
    // 3) temporal heads
    temporal_attn<<<Bsz * Cc * H2d, 256, smemT>>>();
    // 4) SPD log bias + spatial heads
    spatial_riemann<<<Bsz * Nn, 256, smemS>>>(x, hsc);
    // 5) split attn output and fc_w to bf16 hi|lo
    {
        size_t tot = (size_t)MROWS * Dd;
        conv_split<<<(unsigned)(tot / 512), 256>>>(p_attn, p_abuf, tot);
        size_t totw = (size_t)Dd * Dd;
        conv_split<<<(unsigned)(totw / 512), 256>>>(fc_w, p_wbuf, totw);
    }
    // 6) output projection via mma.sync bf16x3
    {
        dim3 grid(Dd / BNg, MROWS / BMg);   // (4, 512)
        gemm_mma<<<grid, 256, smemG>>>(p_abuf, p_wbuf, fc_b, out, Dd);
    }
}

// round 8
// speedup vs baseline: 2.0865x; 1.1121x over previous
#include <cuda_runtime.h>
#include <cuda_bf16.h>
#include <cstdint>
#include <cstddef>
#include <math.h>

#define H2d 4
#define Bsz 16
#define Cc 64
#define Nn 64
#define Dd 512
#define Ll (Nn*Cc)            // 4096
#define M3 (3*Dd)             // 1536
#define LDm 68                // padded smem leading dim (floats)
#define SCALE_ATT 0.125f      // 1/sqrt(64)
#define SPD_EPSF 1e-5f

#define MROWS (Bsz*Ll)        // 65536
#define K2 1024               // stored: [hi(512) | lo(512)]
#define BK 64                 // bf16 K per chunk
#define NCH 24                // compute chunks: 3 phases x 8 chunks of 64
#define BMg 128
#define BNg 128
#define APITCH 72             // bf16 units per smem row (64 + 8 pad) -> 144B pitch
#define STG_TILE (128*APITCH) // bf16 elems per tile per stage
#define STAGES 3

// ---------------- scratch (static device memory; no allocations) ----------------
__device__ float g_qkv[(size_t)Bsz * Ll * M3];            // (B, L, 1536) fp32
__device__ float g_attn[(size_t)Bsz * Ll * Dd];           // (B, L, 512)  fp32
__device__ __nv_bfloat16 g_abuf[(size_t)MROWS * K2];      // bf16 hi|lo activations
__device__ __nv_bfloat16 g_wbuf[(size_t)M3 * K2];         // bf16 hi|lo weights

// =================================================================
// PTX helpers (plain PTX only: cp.async + mma.sync + ldmatrix)
// =================================================================
__device__ __forceinline__ uint32_t smem_u32(const void* p) {
    uint32_t a;
    asm("{ .reg .u64 t; cvta.to.shared.u64 t, %1; cvt.u32.u64 %0, t; }" : "=r"(a) : "l"(p));
    return a;
}
#define CP_ASYNC16(dst, src) \
    asm volatile("cp.async.cg.shared.global [%0], [%1], 16;" :: "r"(dst), "l"(src))
#define CP_COMMIT() asm volatile("cp.async.commit_group;" ::: "memory")
#define CP_WAIT1()  asm volatile("cp.async.wait_group 1;" ::: "memory")

__device__ __forceinline__ void ldsm_x4(uint32_t& r0, uint32_t& r1, uint32_t& r2,
                                        uint32_t& r3, uint32_t addr) {
    asm volatile("ldmatrix.sync.aligned.m8n8.x4.shared.b16 {%0,%1,%2,%3}, [%4];"
                 : "=r"(r0), "=r"(r1), "=r"(r2), "=r"(r3) : "r"(addr));
}
__device__ __forceinline__ void mma16816(float c[4], uint32_t a0, uint32_t a1,
                                         uint32_t a2, uint32_t a3,
                                         uint32_t b0, uint32_t b1) {
    asm volatile(
        "mma.sync.aligned.m16n8k16.row.col.f32.bf16.bf16.f32 "
        "{%0,%1,%2,%3}, {%4,%5,%6,%7}, {%8,%9}, {%0,%1,%2,%3};"
        : "+f"(c[0]), "+f"(c[1]), "+f"(c[2]), "+f"(c[3])
        : "r"(a0), "r"(a1), "r"(a2), "r"(a3), "r"(b0), "r"(b1));
}

// =================================================================
// fp32 -> bf16 hi|lo split. dst: [rows][1024] = [hi 512 | lo 512]
// =================================================================
__global__ void conv_split(const float* __restrict__ src, __nv_bfloat16* __restrict__ dst,
                           size_t total)
{
    size_t i = (size_t)blockIdx.x * blockDim.x + threadIdx.x;
    size_t e = i * 2;
    if (e >= total) return;
    size_t m = e >> 9;          // /512
    int k = (int)(e & 511);
    float2 v = *(const float2*)(src + e);
    __nv_bfloat16 h0 = __float2bfloat16(v.x);
    __nv_bfloat16 h1 = __float2bfloat16(v.y);
    __nv_bfloat16 l0 = __float2bfloat16(v.x - __bfloat162float(h0));
    __nv_bfloat16 l1 = __float2bfloat16(v.y - __bfloat162float(h1));
    __nv_bfloat162 hh; hh.x = h0; hh.y = h1;
    __nv_bfloat162 ll; ll.x = l0; ll.y = l1;
    __nv_bfloat16* base = dst + m * K2 + k;
    *(__nv_bfloat162*)(base)       = hh;
    *(__nv_bfloat162*)(base + 512) = ll;
}

// =================================================================
// mma.sync bf16x3 GEMM: C = A @ W^T + bias, fp32-accurate via
// 3 K-phases over [hi|lo] storage: hi*hi + lo*hi + hi*lo.
// 128x128 CTA tile, 8 warps of 64x32, BK=64, 3-stage cp.async, ldmatrix.
// =================================================================
__global__ __launch_bounds__(256, 2) void gemm_mma(
    const __nv_bfloat16* __restrict__ A, const __nv_bfloat16* __restrict__ W,
    const float* __restrict__ bias, float* __restrict__ C, int Nout)
{
    extern __shared__ __nv_bfloat16 smg[];
    const int tid = threadIdx.x;
    const int wid = tid >> 5, lane = tid & 31;
    const int g = lane >> 2, tig = lane & 3;
    const int warp_m = wid >> 2, warp_n = wid & 3;     // 2 x 4 warps
    const int bc = blockIdx.x, br = blockIdx.y;

    const __nv_bfloat16* gAb = A + (size_t)(br * BMg) * K2;
    const __nv_bfloat16* gBb = W + (size_t)(bc * BNg) * K2;

    const uint32_t smb = smem_u32(smg);

    // per-chunk segment offsets: phase 0: hiA*hiW, 1: loA*hiW, 2: hiA*loW
    auto load_chunk = [&](int kc, int s) {
        const int phase = kc >> 3, k8 = kc & 7;
        const int aoff = ((phase == 1) ? 512 : 0) + k8 * BK;
        const int boff = ((phase == 2) ? 512 : 0) + k8 * BK;
        const uint32_t smA = smb + (uint32_t)(s * 2 * STG_TILE) * 2;
        const uint32_t smB = smA + (uint32_t)STG_TILE * 2;
        const __nv_bfloat16* gA = gAb + aoff;
        const __nv_bfloat16* gB = gBb + boff;
#pragma unroll
        for (int i = 0; i < 4; i++) {       // A: 128 rows x 8 x 16B
            int idx = i * 256 + tid;
            int r = idx >> 3, c16 = idx & 7;
            CP_ASYNC16(smA + r * (APITCH * 2) + c16 * 16, gA + (size_t)r * K2 + c16 * 8);
        }
#pragma unroll
        for (int i = 0; i < 4; i++) {       // B: 128 rows x 8 x 16B
            int idx = i * 256 + tid;
            int r = idx >> 3, c16 = idx & 7;
            CP_ASYNC16(smB + r * (APITCH * 2) + c16 * 16, gB + (size_t)r * K2 + c16 * 8);
        }
    };

    float acc[4][4][4];
#pragma unroll
    for (int mt = 0; mt < 4; mt++)
#pragma unroll
        for (int nt = 0; nt < 4; nt++)
#pragma unroll
            for (int q = 0; q < 4; q++) acc[mt][nt][q] = 0.f;

    // ldmatrix lane address components
    const int a_row = warp_m * 64 + (lane & 15);       // + mt*16
    const int a_kof = (lane >> 4) * 8;                 // + ks*16
    const int b_col = warp_n * 32 + (lane & 7) + ((lane >> 4) << 3);  // + ntp*16
    const int b_kof = ((lane >> 3) & 1) * 8;           // + ks*16

    load_chunk(0, 0); CP_COMMIT();
    load_chunk(1, 1); CP_COMMIT();

    for (int kc = 0; kc < NCH; kc++) {
        CP_WAIT1();            // chunk kc resident
        __syncthreads();
        if (kc + 2 < NCH) load_chunk(kc + 2, (kc + 2) % STAGES);
        CP_COMMIT();

        const int s = kc % STAGES;
        const uint32_t smA = smb + (uint32_t)(s * 2 * STG_TILE) * 2;
        const uint32_t smB = smA + (uint32_t)STG_TILE * 2;

#pragma unroll
        for (int ks = 0; ks < 4; ks++) {
            const int kb = ks * 16;
            uint32_t af[4][4], bf[2][4];
#pragma unroll
            for (int mt = 0; mt < 4; mt++) {
                uint32_t addr = smA + (uint32_t)(((a_row + mt * 16) * APITCH) + kb + a_kof) * 2;
                ldsm_x4(af[mt][0], af[mt][1], af[mt][2], af[mt][3], addr);
            }
#pragma unroll
            for (int ntp = 0; ntp < 2; ntp++) {
                uint32_t addr = smB + (uint32_t)(((b_col + ntp * 16) * APITCH) + kb + b_kof) * 2;
                ldsm_x4(bf[ntp][0], bf[ntp][1], bf[ntp][2], bf[ntp][3], addr);
            }
#pragma unroll
            for (int mt = 0; mt < 4; mt++)
#pragma unroll
                for (int ntp = 0; ntp < 2; ntp++) {
                    mma16816(acc[mt][2 * ntp],     af[mt][0], af[mt][1], af[mt][2], af[mt][3],
                             bf[ntp][0], bf[ntp][1]);
                    mma16816(acc[mt][2 * ntp + 1], af[mt][0], af[mt][1], af[mt][2], af[mt][3],
                             bf[ntp][2], bf[ntp][3]);
                }
        }
    }

    // ---- epilogue: direct register -> global with bias ----
#pragma unroll
    for (int mt = 0; mt < 4; mt++) {
        int row0 = br * BMg + warp_m * 64 + mt * 16 + g;
#pragma unroll
        for (int nt = 0; nt < 4; nt++) {
            int col = bc * BNg + warp_n * 32 + nt * 8 + 2 * tig;
            float b0 = bias[col], b1 = bias[col + 1];
            *(float2*)(C + (size_t)row0 * Nout + col) =
                make_float2(acc[mt][nt][0] + b0, acc[mt][nt][1] + b1);
            *(float2*)(C + (size_t)(row0 + 8) * Nout + col) =
                make_float2(acc[mt][nt][2] + b0, acc[mt][nt][3] + b1);
        }
    }
}

// =================================================================
// 64x64 smem matmul helper (validated)
// =================================================================
__device__ __forceinline__ void mm64(float* __restrict__ dst,
                                     const float* __restrict__ Am,
                                     const float* __restrict__ Bm,
                                     int tx, int ty, float dscale, float diagadd)
{
    float acc[4][4] = {};
#pragma unroll 8
    for (int k = 0; k < 64; k++) {
        float4 bv = *(const float4*)(Bm + k * LDm + 4 * tx);
        float a0 = Am[(4 * ty + 0) * LDm + k];
        float a1 = Am[(4 * ty + 1) * LDm + k];
        float a2 = Am[(4 * ty + 2) * LDm + k];
        float a3 = Am[(4 * ty + 3) * LDm + k];
        acc[0][0] += a0 * bv.x; acc[0][1] += a0 * bv.y; acc[0][2] += a0 * bv.z; acc[0][3] += a0 * bv.w;
        acc[1][0] += a1 * bv.x; acc[1][1] += a1 * bv.y; acc[1][2] += a1 * bv.z; acc[1][3] += a1 * bv.w;
        acc[2][0] += a2 * bv.x; acc[2][1] += a2 * bv.y; acc[2][2] += a2 * bv.z; acc[2][3] += a2 * bv.w;
        acc[3][0] += a3 * bv.x; acc[3][1] += a3 * bv.y; acc[3][2] += a3 * bv.z; acc[3][3] += a3 * bv.w;
    }
#pragma unroll
    for (int i = 0; i < 4; i++)
#pragma unroll
        for (int j = 0; j < 4; j++) {
            int r = 4 * ty + i, c = 4 * tx + j;
            dst[r * LDm + c] = acc[i][j] * dscale + ((r == c) ? diagadd : 0.f);
        }
    __syncthreads();
}

__device__ __forceinline__ void softmax_rows(float acc[4][4])
{
#pragma unroll
    for (int i = 0; i < 4; i++) {
        float m = fmaxf(fmaxf(acc[i][0], acc[i][1]), fmaxf(acc[i][2], acc[i][3]));
#pragma unroll
        for (int off = 8; off > 0; off >>= 1)
            m = fmaxf(m, __shfl_xor_sync(0xffffffffu, m, off, 16));
        float s = 0.f;
#pragma unroll
        for (int j = 0; j < 4; j++) { acc[i][j] = __expf(acc[i][j] - m); s += acc[i][j]; }
#pragma unroll
        for (int off = 8; off > 0; off >>= 1)
            s += __shfl_xor_sync(0xffffffffu, s, off, 16);
        float inv = 1.f / s;
#pragma unroll
        for (int j = 0; j < 4; j++) acc[i][j] *= inv;
    }
}

// =================================================================
// Temporal attention (unchanged, validated)
// =================================================================
__global__ __launch_bounds__(256, 2) void temporal_attn()
{
    extern __shared__ float smT[];
    float* Q  = smT;
    float* Kt = Q  + 64 * LDm;
    float* V  = Kt + 64 * LDm;
    float* P  = V  + 64 * LDm;
    const int tid = threadIdx.x, tx = tid & 15, ty = tid >> 4;
    const int h = blockIdx.x & 3;
    const int c = (blockIdx.x >> 2) & 63;
    const int b = blockIdx.x >> 8;

    const float* qk = g_qkv + (size_t)b * Ll * M3 + h * 64;
#pragma unroll
    for (int it = 0; it < 16; it++) {
        int idx = it * 256 + tid;
        int nn = idx >> 6, e = idx & 63;
        const float* p = qk + (size_t)(nn * Cc + c) * M3 + e;
        Q [nn * LDm + e]  = p[0];
        Kt[e  * LDm + nn] = p[Dd];
        V [nn * LDm + e]  = p[2 * Dd];
    }
    __syncthreads();

    float acc[4][4] = {};
#pragma unroll 8
    for (int k = 0; k < 64; k++) {
        float4 bv = *(const float4*)(Kt + k * LDm + 4 * tx);
        float a0 = Q[(4 * ty + 0) * LDm + k];
        float a1 = Q[(4 * ty + 1) * LDm + k];
        float a2 = Q[(4 * ty + 2) * LDm + k];
        float a3 = Q[(4 * ty + 3) * LDm + k];
        acc[0][0] += a0 * bv.x; acc[0][1] += a0 * bv.y; acc[0][2] += a0 * bv.z; acc[0][3] += a0 * bv.w;
        acc[1][0] += a1 * bv.x; acc[1][1] += a1 * bv.y; acc[1][2] += a1 * bv.z; acc[1][3] += a1 * bv.w;
        acc[2][0] += a2 * bv.x; acc[2][1] += a2 * bv.y; acc[2][2] += a2 * bv.z; acc[2][3] += a2 * bv.w;
        acc[3][0] += a3 * bv.x; acc[3][1] += a3 * bv.y; acc[3][2] += a3 * bv.z; acc[3][3] += a3 * bv.w;
    }
#pragma unroll
    for (int i = 0; i < 4; i++)
#pragma unroll
        for (int j = 0; j < 4; j++) acc[i][j] *= SCALE_ATT;

    softmax_rows(acc);

#pragma unroll
    for (int i = 0; i < 4; i++)
#pragma unroll
        for (int j = 0; j < 4; j++)
            P[(4 * ty + i) * LDm + 4 * tx + j] = acc[i][j];
    __syncthreads();

    float o[4][4] = {};
#pragma unroll 8
    for (int k = 0; k < 64; k++) {
        float4 bv = *(const float4*)(V + k * LDm + 4 * tx);
        float a0 = P[(4 * ty + 0) * LDm + k];
        float a1 = P[(4 * ty + 1) * LDm + k];
        float a2 = P[(4 * ty + 2) * LDm + k];
        float a3 = P[(4 * ty + 3) * LDm + k];
        o[0][0] += a0 * bv.x; o[0][1] += a0 * bv.y; o[0][2] += a0 * bv.z; o[0][3] += a0 * bv.w;
        o[1][0] += a1 * bv.x; o[1][1] += a1 * bv.y; o[1][2] += a1 * bv.z; o[1][3] += a1 * bv.w;
        o[2][0] += a2 * bv.x; o[2][1] += a2 * bv.y; o[2][2] += a2 * bv.z; o[2][3] += a2 * bv.w;
        o[3][0] += a3 * bv.x; o[3][1] += a3 * bv.y; o[3][2] += a3 * bv.z; o[3][3] += a3 * bv.w;
    }
#pragma unroll
    for (int i = 0; i < 4; i++) {
        size_t l = (size_t)(4 * ty + i) * Cc + c;
        *(float4*)(g_attn + ((size_t)b * Ll + l) * Dd + h * 64 + 4 * tx) =
            make_float4(o[i][0], o[i][1], o[i][2], o[i][3]);
    }
}

// =================================================================
// Spatial branch: NS 5 iters, Gregory 6 terms (validated R7)
// =================================================================
__global__ __launch_bounds__(256, 2) void spatial_riemann(
    const float* __restrict__ x, const float* __restrict__ head_scales)
{
    extern __shared__ float smS[];
    float* B0 = smS;
    float* B1 = B0 + 64 * LDm;
    float* B2 = B1 + 64 * LDm;
    float* B3 = B2 + 64 * LDm;
    float* LM = B3 + 64 * LDm;
    float* red = LM + 64 * LDm;
    __shared__ float s_alpha;

    const int tid = threadIdx.x, tx = tid & 15, ty = tid >> 4;
    const int n = blockIdx.x & 63, b = blockIdx.x >> 6;
    const float* xb = x + ((size_t)b * Ll + n * Cc) * Dd;

    float sacc[4][4] = {};
    for (int kc = 0; kc < 8; kc++) {
#pragma unroll
        for (int it = 0; it < 16; it++) {
            int idx = it * 256 + tid;
            int r = idx >> 6, col = idx & 63;
            float v = xb[(size_t)r * Dd + kc * 64 + col];
            B2[r * LDm + col] = v;
            B3[col * LDm + r] = v;
        }
        __syncthreads();
#pragma unroll 8
        for (int k = 0; k < 64; k++) {
            float4 bv = *(const float4*)(B3 + k * LDm + 4 * tx);
            float a0 = B2[(4 * ty + 0) * LDm + k];
            float a1 = B2[(4 * ty + 1) * LDm + k];
            float a2 = B2[(4 * ty + 2) * LDm + k];
            float a3 = B2[(4 * ty + 3) * LDm + k];
            sacc[0][0] += a0 * bv.x; sacc[0][1] += a0 * bv.y; sacc[0][2] += a0 * bv.z; sacc[0][3] += a0 * bv.w;
            sacc[1][0] += a1 * bv.x; sacc[1][1] += a1 * bv.y; sacc[1][2] += a1 * bv.z; sacc[1][3] += a1 * bv.w;
            sacc[2][0] += a2 * bv.x; sacc[2][1] += a2 * bv.y; sacc[2][2] += a2 * bv.z; sacc[2][3] += a2 * bv.w;
            sacc[3][0] += a3 * bv.x; sacc[3][1] += a3 * bv.y; sacc[3][2] += a3 * bv.z; sacc[3][3] += a3 * bv.w;
        }
        __syncthreads();
    }
#pragma unroll
    for (int i = 0; i < 4; i++)
#pragma unroll
        for (int j = 0; j < 4; j++) {
            int r = 4 * ty + i, c = 4 * tx + j;
            float v = sacc[i][j] * (1.f / (float)Dd);
            if (r == c) v += 1.f + SPD_EPSF;
            B0[r * LDm + c] = v;
        }
    __syncthreads();

    {
        int r = tid >> 2, seg = tid & 3;
        float s = 0.f;
#pragma unroll
        for (int j = 0; j < 16; j++) s += fabsf(B0[r * LDm + seg * 16 + j]);
        red[tid] = s;
    }
    __syncthreads();
    if (tid == 0) {
        float rmax = 0.f;
        for (int r = 0; r < 64; r++)
            rmax = fmaxf(rmax, red[4 * r] + red[4 * r + 1] + red[4 * r + 2] + red[4 * r + 3]);
        s_alpha = 2.f / (1.f + rmax);
    }
    __syncthreads();
    float alpha = s_alpha;

#pragma unroll
    for (int i = 0; i < 4; i++)
#pragma unroll
        for (int j = 0; j < 4; j++) {
            int r = 4 * ty + i, c = 4 * tx + j;
            B1[r * LDm + c] = (r == c) ? alpha : 0.f;
        }
    __syncthreads();

    for (int it = 0; it < 5; it++) {
        mm64(B2, B0, B1, tx, ty, 1.f, 0.f);
        mm64(B3, B1, B2, tx, ty, 1.f, 0.f);
#pragma unroll
        for (int i = 0; i < 4; i++)
#pragma unroll
            for (int j = 0; j < 4; j++) {
                int r = 4 * ty + i, c = 4 * tx + j;
                B1[r * LDm + c] = 2.f * B1[r * LDm + c] - B3[r * LDm + c];
            }
        __syncthreads();
    }

#pragma unroll
    for (int i = 0; i < 4; i++)
#pragma unroll
        for (int j = 0; j < 4; j++) {
            int r = 4 * ty + i, c = 4 * tx + j;
            B2[r * LDm + c] = ((r == c) ? 1.f : 0.f) - 2.f * B1[r * LDm + c];
        }
    __syncthreads();

    mm64(B0, B2, B2, tx, ty, 1.f, 0.f);   // W = Z^2

#pragma unroll
    for (int i = 0; i < 4; i++)
#pragma unroll
        for (int j = 0; j < 4; j++) {
            int r = 4 * ty + i, c = 4 * tx + j;
            B3[r * LDm + c] = (r == c) ? (1.f / 11.f) : 0.f;
        }
    __syncthreads();
    {
        float* cur = B3; float* oth = B1;
        for (int m = 4; m >= 0; m--) {
            mm64(oth, cur, B0, tx, ty, 1.f, 1.f / (float)(2 * m + 1));
            float* t = cur; cur = oth; oth = t;
        }
        mm64(LM, B2, cur, tx, ty, 2.f, 0.f);   // Lm = 2 Z P
    }

    const float* qk = g_qkv + (size_t)b * Ll * M3 + H2d * 64;
    for (int h = 0; h < H2d; h++) {
        float hs = head_scales[h];
#pragma unroll
        for (int it = 0; it < 16; it++) {
            int idx = it * 256 + tid;
            int r = idx >> 6, e = idx & 63;
            const float* p = qk + (size_t)(n * Cc + r) * M3 + h * 64 + e;
            B0[r * LDm + e] = p[0];
            B2[e * LDm + r] = p[Dd];
            B3[r * LDm + e] = p[2 * Dd];
        }
        __syncthreads();

        float a4[4][4] = {};
#pragma unroll 8
        for (int k = 0; k < 64; k++) {
            float4 bv = *(const float4*)(B2 + k * LDm + 4 * tx);
            float a0 = B0[(4 * ty + 0) * LDm + k];
            float a1 = B0[(4 * ty + 1) * LDm + k];
            float a2 = B0[(4 * ty + 2) * LDm + k];
            float a3 = B0[(4 * ty + 3) * LDm + k];
            a4[0][0] += a0 * bv.x; a4[0][1] += a0 * bv.y; a4[0][2] += a0 * bv.z; a4[0][3] += a0 * bv.w;
            a4[1][0] += a1 * bv.x; a4[1][1] += a1 * bv.y; a4[1][2] += a1 * bv.z; a4[1][3] += a1 * bv.w;
            a4[2][0] += a2 * bv.x; a4[2][1] += a2 * bv.y; a4[2][2] += a2 * bv.z; a4[2][3] += a2 * bv.w;
            a4[3][0] += a3 * bv.x; a4[3][1] += a3 * bv.y; a4[3][2] += a3 * bv.z; a4[3][3] += a3 * bv.w;
        }
#pragma unroll
        for (int i = 0; i < 4; i++)
#pragma unroll
            for (int j = 0; j < 4; j++)
                a4[i][j] = a4[i][j] * SCALE_ATT + hs * LM[(4 * ty + i) * LDm + 4 * tx + j];

        softmax_rows(a4);

#pragma unroll
        for (int i = 0; i < 4; i++)
#pragma unroll
            for (int j = 0; j < 4; j++)
                B1[(4 * ty + i) * LDm + 4 * tx + j] = a4[i][j];
        __syncthreads();

        float o[4][4] = {};
#pragma unroll 8
        for (int k = 0; k < 64; k++) {
            float4 bv = *(const float4*)(B3 + k * LDm + 4 * tx);
            float a0 = B1[(4 * ty + 0) * LDm + k];
            float a1 = B1[(4 * ty + 1) * LDm + k];
            float a2 = B1[(4 * ty + 2) * LDm + k];
            float a3 = B1[(4 * ty + 3) * LDm + k];
            o[0][0] += a0 * bv.x; o[0][1] += a0 * bv.y; o[0][2] += a0 * bv.z; o[0][3] += a0 * bv.w;
            o[1][0] += a1 * bv.x; o[1][1] += a1 * bv.y; o[1][2] += a1 * bv.z; o[1][3] += a1 * bv.w;
            o[2][0] += a2 * bv.x; o[2][1] += a2 * bv.y; o[2][2] += a2 * bv.z; o[2][3] += a2 * bv.w;
            o[3][0] += a3 * bv.x; o[3][1] += a3 * bv.y; o[3][2] += a3 * bv.z; o[3][3] += a3 * bv.w;
        }
#pragma unroll
        for (int i = 0; i < 4; i++) {
            size_t l = (size_t)n * Cc + 4 * ty + i;
            *(float4*)(g_attn + ((size_t)b * Ll + l) * Dd + (H2d + h) * 64 + 4 * tx) =
                make_float4(o[i][0], o[i][1], o[i][2], o[i][3]);
        }
        __syncthreads();
    }
}

// =================================================================
// launch
// =================================================================
extern "C" void kernel_launch(void* const* d_in, const int* in_sizes, int n_in,
                              void* d_out, int out_size)
{
    const float* x     = (const float*)d_in[0];
    const float* qkv_w = (const float*)d_in[1];
    const float* qkv_b = (const float*)d_in[2];
    const float* fc_w  = (const float*)d_in[3];
    const float* fc_b  = (const float*)d_in[4];
    const float* hsc   = (const float*)d_in[5];
    float* out = (float*)d_out;

    float* p_qkv = nullptr;
    float* p_attn = nullptr;
    __nv_bfloat16* p_abuf = nullptr;
    __nv_bfloat16* p_wbuf = nullptr;
    cudaGetSymbolAddress((void**)&p_qkv, g_qkv);
    cudaGetSymbolAddress((void**)&p_attn, g_attn);
    cudaGetSymbolAddress((void**)&p_abuf, g_abuf);
    cudaGetSymbolAddress((void**)&p_wbuf, g_wbuf);

    const int smemT = 4 * 64 * LDm * (int)sizeof(float);
    const int smemS = 5 * 64 * LDm * (int)sizeof(float) + 256 * 4;
    const int smemG = STAGES * 2 * STG_TILE * (int)sizeof(__nv_bfloat16);   // 110592
    cudaFuncSetAttribute(temporal_attn, cudaFuncAttributeMaxDynamicSharedMemorySize, smemT);
    cudaFuncSetAttribute(spatial_riemann, cudaFuncAttributeMaxDynamicSharedMemorySize, smemS);
    cudaFuncSetAttribute(gemm_mma, cudaFuncAttributeMaxDynamicSharedMemorySize, smemG);

    // 1) split x and qkv_w to bf16 hi|lo
    {
        size_t tot = (size_t)MROWS * Dd;
        conv_split<<<(unsigned)(tot / 512), 256>>>(x, p_abuf, tot);
        size_t totw = (size_t)M3 * Dd;
        conv_split<<<(unsigned)(totw / 512), 256>>>(qkv_w, p_wbuf, totw);
    }
    // 2) QKV projection via mma.sync bf16x3
    {
        dim3 grid(M3 / BNg, MROWS / BMg);   // (12, 512)
        gemm_mma<<<grid, 256, smemG>>>(p_abuf, p_wbuf, qkv_b, p_qkv, M3);
    }
    // 3) temporal heads
    temporal_attn<<<Bsz * Cc * H2d, 256, smemT>>>();
    // 4) SPD log bias + spatial heads
    spatial_riemann<<<Bsz * Nn, 256, smemS>>>(x, hsc);
    // 5) split attn output and fc_w to bf16 hi|lo
    {
        size_t tot = (size_t)MROWS * Dd;
        conv_split<<<(unsigned)(tot / 512), 256>>>(p_attn, p_abuf, tot);
        size_t totw = (size_t)Dd * Dd;
        conv_split<<<(unsigned)(totw / 512), 256>>>(fc_w, p_wbuf, totw);
    }
    // 6) output projection via mma.sync bf16x3
    {
        dim3 grid(Dd / BNg, MROWS / BMg);   // (4, 512)
        gemm_mma<<<grid, 256, smemG>>>(p_abuf, p_wbuf, fc_b, out, Dd);
    }
}